// round 7
// baseline (speedup 1.0000x reference)
#include <cuda_runtime.h>
#include <cstdint>

#define BDIM 256
#define FDIM 4
#define MDIM 256
#define DDIM 8192
#define WDIM 256          // DDIM/32 packed words
#define NITERS 10

// Scratch (device globals -- allocation is forbidden)
__device__ float g_est[BDIM * FDIM * DDIM];       // 32 MB  float est (stage0 only)
__device__ float g_new[BDIM * FDIM * DDIM];       // 32 MB  stage-0 new_est
__device__ float g_sim[BDIM * FDIM * MDIM];       // 1 MB
__device__ unsigned g_pS[BDIM * FDIM * WDIM];     // packed new_est sign bits
__device__ unsigned g_pM[BDIM * FDIM * WDIM];     // packed new_est nonzero mask
__device__ unsigned g_eS[BDIM * FDIM * WDIM];     // packed est sign bits (canonical: S&M)
__device__ unsigned g_eM[BDIM * FDIM * WDIM];     // packed est nonzero mask
__device__ unsigned g_iS[BDIM * WDIM];            // packed inp sign bits
__device__ unsigned g_cbSt[FDIM * WDIM * MDIM];   // cb sign bits transposed [f][w][m]
__device__ signed char g_cbT8[FDIM * DDIM * MDIM];// cb int8 transposed [f][d][m]
__device__ signed char g_simLo[BDIM * FDIM * MDIM];
__device__ signed char g_simHi[BDIM * FDIM * MDIM];   // sim = 128*hi + lo
__device__ int g_done;
__device__ int g_diff;
__device__ int g_k;

// ---------------------------------------------------------------------------
// init: est[b,f,d] = sum_m cb[f,m,d]; reset flags
// ---------------------------------------------------------------------------
__global__ void init_est_kernel(const float* __restrict__ cb) {
    int idx = blockIdx.x * blockDim.x + threadIdx.x;
    if (idx == 0) { g_done = 0; g_diff = 0; g_k = 0; }
    if (idx >= FDIM * DDIM) return;
    int f = idx >> 13;
    int d = idx & (DDIM - 1);
    const float* p = cb + ((size_t)f * MDIM) * DDIM + d;
    float s = 0.f;
    for (int m = 0; m < MDIM; m++) s += p[(size_t)m * DDIM];
    float* q = g_est + (size_t)f * DDIM + d;
    for (int b = 0; b < BDIM; b++) q[(size_t)b * FDIM * DDIM] = s;
}

// ---------------------------------------------------------------------------
// pack cb sign bits: g_cbSt[f][w][m], bit j <-> d = w*32+j, bit=1 means negative
// ---------------------------------------------------------------------------
__global__ void pack_cb_kernel(const float* __restrict__ cb) {
    int idx = blockIdx.x * blockDim.x + threadIdx.x;  // (f*M+m)*8192 + d
    float v = cb[idx];
    unsigned neg = __ballot_sync(0xffffffffu, v < 0.f);
    if ((threadIdx.x & 31) == 0) {
        int fm = idx >> 13;
        int d = idx & (DDIM - 1);
        int f = fm >> 8;
        int m = fm & 255;
        g_cbSt[((size_t)f * WDIM + (d >> 5)) * MDIM + m] = neg;
    }
}

// ---------------------------------------------------------------------------
// pack inp sign bits: g_iS[b][w]
// ---------------------------------------------------------------------------
__global__ void pack_inp_kernel(const float* __restrict__ inp) {
    int idx = blockIdx.x * blockDim.x + threadIdx.x;  // b*8192 + d
    unsigned neg = __ballot_sync(0xffffffffu, inp[idx] < 0.f);
    if ((threadIdx.x & 31) == 0) {
        int b = idx >> 13;
        int d = idx & (DDIM - 1);
        g_iS[(size_t)b * WDIM + (d >> 5)] = neg;
    }
}

// ---------------------------------------------------------------------------
// cb -> int8 transposed [f][d][m]
// ---------------------------------------------------------------------------
__global__ void cb_t8_kernel(const float* __restrict__ cb) {
    __shared__ signed char t[32][33];
    int d0 = blockIdx.x * 32;
    int m0 = blockIdx.y * 32;
    int f = blockIdx.z;
    int tx = threadIdx.x & 31;
    int ty = threadIdx.x >> 5;
    for (int k = 0; k < 4; k++) {
        int m = m0 + ty * 4 + k;
        t[ty * 4 + k][tx] = (signed char)cb[((size_t)f * MDIM + m) * DDIM + d0 + tx];
    }
    __syncthreads();
    for (int k = 0; k < 4; k++) {
        int d = d0 + ty * 4 + k;
        g_cbT8[((size_t)f * DDIM + d) * MDIM + m0 + tx] = t[tx][ty * 4 + k];
    }
}

// ---------------------------------------------------------------------------
__global__ void zero_sim_kernel() {
    int idx = blockIdx.x * blockDim.x + threadIdx.x;
    if (idx < BDIM * FDIM * MDIM) g_sim[idx] = 0.f;
}

// ---------------------------------------------------------------------------
// stage-0 new_est (float, large values)  -- proven
// ---------------------------------------------------------------------------
__global__ void newest_f32_kernel(const float* __restrict__ inp) {
    if (g_done) return;
    int idx = blockIdx.x * blockDim.x + threadIdx.x;
    int b = idx >> 13;
    int d = idx & (DDIM - 1);
    const float* eb = g_est + ((size_t)b * FDIM) * DDIM + d;
    float e0 = eb[0];
    float e1 = eb[DDIM];
    float e2 = eb[2 * DDIM];
    float e3 = eb[3 * DDIM];
    float x = inp[idx];
    float p01 = e0 * e1;
    float p23 = e2 * e3;
    float* nb = g_new + ((size_t)b * FDIM) * DDIM + d;
    nb[0]        = x * (e1 * p23);
    nb[DDIM]     = x * (e0 * p23);
    nb[2 * DDIM] = x * (p01 * e3);
    nb[3 * DDIM] = x * (p01 * e2);
}

// ---------------------------------------------------------------------------
// stage-0 GEMM1 (float, split-K=8 atomicAdd) -- proven
// ---------------------------------------------------------------------------
__global__ void gemm1_f32_kernel(const float* __restrict__ cb) {
    if (g_done) return;
    const float* A = g_new;
    int bt = blockIdx.x >> 2;
    int mt = blockIdx.x & 3;
    int f = blockIdx.y;
    int b0 = bt * 64;
    int m0 = mt * 64;
    int k0 = blockIdx.z * (DDIM / 8);

    __shared__ float As[32][68];
    __shared__ float Bs[32][68];

    int tx = threadIdx.x & 15;
    int ty = threadIdx.x >> 4;

    float acc[4][4];
    for (int i = 0; i < 4; i++)
        for (int j = 0; j < 4; j++) acc[i][j] = 0.f;

    for (int kk = 0; kk < DDIM / 8; kk += 32) {
        for (int e = threadIdx.x; e < 2048; e += 256) {
            int r = e >> 5;
            int c = e & 31;
            As[c][r] = A[((size_t)(b0 + r) * FDIM + f) * DDIM + k0 + kk + c];
            Bs[c][r] = cb[((size_t)f * MDIM + m0 + r) * DDIM + k0 + kk + c];
        }
        __syncthreads();
        #pragma unroll
        for (int k = 0; k < 32; k++) {
            float a0 = As[k][tx * 4 + 0];
            float a1 = As[k][tx * 4 + 1];
            float a2 = As[k][tx * 4 + 2];
            float a3 = As[k][tx * 4 + 3];
            float c0 = Bs[k][ty * 4 + 0];
            float c1 = Bs[k][ty * 4 + 1];
            float c2 = Bs[k][ty * 4 + 2];
            float c3 = Bs[k][ty * 4 + 3];
            acc[0][0] += a0 * c0; acc[0][1] += a0 * c1; acc[0][2] += a0 * c2; acc[0][3] += a0 * c3;
            acc[1][0] += a1 * c0; acc[1][1] += a1 * c1; acc[1][2] += a1 * c2; acc[1][3] += a1 * c3;
            acc[2][0] += a2 * c0; acc[2][1] += a2 * c1; acc[2][2] += a2 * c2; acc[2][3] += a2 * c3;
            acc[3][0] += a3 * c0; acc[3][1] += a3 * c1; acc[3][2] += a3 * c2; acc[3][3] += a3 * c3;
        }
        __syncthreads();
    }
    for (int i = 0; i < 4; i++)
        for (int j = 0; j < 4; j++) {
            int b = b0 + tx * 4 + i;
            int m = m0 + ty * 4 + j;
            atomicAdd(&g_sim[((size_t)b * FDIM + f) * MDIM + m], acc[i][j]);
        }
}

// ---------------------------------------------------------------------------
// stage-0 GEMM2 (float) + sign + convergence + float est update -- proven
// ---------------------------------------------------------------------------
__global__ void gemm2_f32_kernel(const float* __restrict__ cb) {
    if (g_done) return;
    int f = blockIdx.z;
    int b0 = blockIdx.y * 64;
    int d0 = blockIdx.x * 64;

    __shared__ float As[32][68];
    __shared__ float Bs[32][68];

    int tx = threadIdx.x & 15;
    int ty = threadIdx.x >> 4;

    float acc[4][4];
    for (int i = 0; i < 4; i++)
        for (int j = 0; j < 4; j++) acc[i][j] = 0.f;

    for (int mb = 0; mb < MDIM; mb += 32) {
        for (int e = threadIdx.x; e < 2048; e += 256) {
            int r = e >> 5;
            int c = e & 31;
            As[c][r] = g_sim[((size_t)(b0 + r) * FDIM + f) * MDIM + mb + c];
        }
        for (int e = threadIdx.x; e < 2048; e += 256) {
            int m = e >> 6;
            int dd = e & 63;
            Bs[m][dd] = cb[((size_t)f * MDIM + mb + m) * DDIM + d0 + dd];
        }
        __syncthreads();
        #pragma unroll
        for (int m = 0; m < 32; m++) {
            float a0 = As[m][ty * 4 + 0];
            float a1 = As[m][ty * 4 + 1];
            float a2 = As[m][ty * 4 + 2];
            float a3 = As[m][ty * 4 + 3];
            float c0 = Bs[m][tx * 4 + 0];
            float c1 = Bs[m][tx * 4 + 1];
            float c2 = Bs[m][tx * 4 + 2];
            float c3 = Bs[m][tx * 4 + 3];
            acc[0][0] += a0 * c0; acc[0][1] += a0 * c1; acc[0][2] += a0 * c2; acc[0][3] += a0 * c3;
            acc[1][0] += a1 * c0; acc[1][1] += a1 * c1; acc[1][2] += a1 * c2; acc[1][3] += a1 * c3;
            acc[2][0] += a2 * c0; acc[2][1] += a2 * c1; acc[2][2] += a2 * c2; acc[2][3] += a2 * c3;
            acc[3][0] += a3 * c0; acc[3][1] += a3 * c1; acc[3][2] += a3 * c2; acc[3][3] += a3 * c3;
        }
        __syncthreads();
    }

    int ldiff = 0;
    for (int i = 0; i < 4; i++) {
        int b = b0 + ty * 4 + i;
        float* erow = g_est + ((size_t)b * FDIM + f) * DDIM + d0 + tx * 4;
        for (int j = 0; j < 4; j++) {
            float v = acc[i][j];
            float s = (v > 0.f) ? 1.f : ((v < 0.f) ? -1.f : 0.f);
            if (s != erow[j]) ldiff = 1;
            erow[j] = s;
        }
    }
    if (ldiff) g_diff = 1;
}

// ---------------------------------------------------------------------------
// float est (ternary) -> packed est bitplanes (canonical S = neg & M)
// ---------------------------------------------------------------------------
__global__ void est_pack_kernel() {
    int idx = blockIdx.x * blockDim.x + threadIdx.x;   // (b*F+f)*8192 + d
    float v = g_est[idx];
    unsigned neg = __ballot_sync(0xffffffffu, v < 0.f);
    unsigned nzm = __ballot_sync(0xffffffffu, v != 0.f);
    if ((threadIdx.x & 31) == 0) {
        int bf = idx >> 13;
        int d = idx & (DDIM - 1);
        g_eS[(size_t)bf * WDIM + (d >> 5)] = neg & nzm;
        g_eM[(size_t)bf * WDIM + (d >> 5)] = nzm;
    }
}

// ---------------------------------------------------------------------------
// stages >= 1: fully bitwise new_est from packed est + packed inp.
// one thread per (b, word); writes 4 factor planes.
// ---------------------------------------------------------------------------
__global__ void newest_bits_kernel() {
    if (g_done) return;
    int idx = blockIdx.x * blockDim.x + threadIdx.x;   // b*WDIM + w
    if (idx >= BDIM * WDIM) return;
    int b = idx >> 8;
    int w = idx & 255;
    size_t base = (size_t)b * FDIM * WDIM + w;
    unsigned s0 = g_eS[base];
    unsigned s1 = g_eS[base + WDIM];
    unsigned s2 = g_eS[base + 2 * WDIM];
    unsigned s3 = g_eS[base + 3 * WDIM];
    unsigned m0 = g_eM[base];
    unsigned m1 = g_eM[base + WDIM];
    unsigned m2 = g_eM[base + 2 * WDIM];
    unsigned m3 = g_eM[base + 3 * WDIM];
    unsigned is = g_iS[(size_t)b * WDIM + w];
    unsigned sAll = is ^ s0 ^ s1 ^ s2 ^ s3;
    unsigned M0 = m1 & m2 & m3;
    unsigned M1 = m0 & m2 & m3;
    unsigned M2 = m0 & m1 & m3;
    unsigned M3 = m0 & m1 & m2;
    g_pS[base]            = (sAll ^ s0) & M0;
    g_pS[base + WDIM]     = (sAll ^ s1) & M1;
    g_pS[base + 2 * WDIM] = (sAll ^ s2) & M2;
    g_pS[base + 3 * WDIM] = (sAll ^ s3) & M3;
    g_pM[base]            = M0;
    g_pM[base + WDIM]     = M1;
    g_pM[base + 2 * WDIM] = M2;
    g_pM[base + 3 * WDIM] = M3;
}

// ---------------------------------------------------------------------------
// packed GEMM1: sim = nz - 2*popc((Sa^Sb)&Ma).  src_est selects est planes
// (final sim) vs new_est planes (iteration).  Writes f32 sim + int8 planes.
// ---------------------------------------------------------------------------
__global__ void gemm1_packed_kernel(int src_est, int respect_done) {
    if (respect_done && g_done) return;
    const unsigned* PS = src_est ? g_eS : g_pS;
    const unsigned* PM = src_est ? g_eM : g_pM;
    int b0 = blockIdx.x * 32;
    int m0 = blockIdx.y * 32;
    int f = blockIdx.z;

    __shared__ unsigned AS[32][33];
    __shared__ unsigned AM[32][33];
    __shared__ unsigned BS[32][33];

    int tx = threadIdx.x & 15;
    int ty = threadIdx.x >> 4;

    int acc[2][2] = {{0, 0}, {0, 0}};
    int accM[2] = {0, 0};

    for (int w0 = 0; w0 < WDIM; w0 += 32) {
        for (int e = threadIdx.x; e < 1024; e += 256) {
            int r = e >> 5;
            int c = e & 31;
            size_t src = ((size_t)(b0 + r) * FDIM + f) * WDIM + w0 + c;
            AS[c][r] = PS[src];
            AM[c][r] = PM[src];
        }
        for (int e = threadIdx.x; e < 1024; e += 256) {
            int w = e >> 5;
            int m = e & 31;
            BS[w][m] = g_cbSt[((size_t)f * WDIM + w0 + w) * MDIM + m0 + m];
        }
        __syncthreads();
        #pragma unroll
        for (int w = 0; w < 32; w++) {
            unsigned sa0 = AS[w][tx * 2 + 0];
            unsigned sa1 = AS[w][tx * 2 + 1];
            unsigned ma0 = AM[w][tx * 2 + 0];
            unsigned ma1 = AM[w][tx * 2 + 1];
            unsigned sb0 = BS[w][ty * 2 + 0];
            unsigned sb1 = BS[w][ty * 2 + 1];
            accM[0] += __popc(ma0);
            accM[1] += __popc(ma1);
            acc[0][0] += __popc((sa0 ^ sb0) & ma0);
            acc[0][1] += __popc((sa0 ^ sb1) & ma0);
            acc[1][0] += __popc((sa1 ^ sb0) & ma1);
            acc[1][1] += __popc((sa1 ^ sb1) & ma1);
        }
        __syncthreads();
    }

    #pragma unroll
    for (int i = 0; i < 2; i++) {
        int b = b0 + tx * 2 + i;
        #pragma unroll
        for (int j = 0; j < 2; j++) {
            int m = m0 + ty * 2 + j;
            int sim = accM[i] - 2 * acc[i][j];
            size_t o = ((size_t)b * FDIM + f) * MDIM + m;
            g_sim[o] = (float)sim;
            int hi = (sim + 64) >> 7;
            int lo = sim - (hi << 7);
            g_simHi[o] = (signed char)hi;
            g_simLo[o] = (signed char)lo;
        }
    }
}

// ---------------------------------------------------------------------------
// packed GEMM2 via dp4a + packed-est epilogue.
// out[b,f,d] = 128*(hi.cbT8) + (lo.cbT8) over m=256.  Integer-exact.
// Epilogue: pack ternary signs to bitplanes via smem nibbles, compare with
// old packed est (convergence), write packed est.
// ---------------------------------------------------------------------------
__global__ void gemm2_dp4a_kernel() {
    if (g_done) return;
    int d0 = blockIdx.x * 64;
    int b0 = blockIdx.y * 64;
    int f = blockIdx.z;

    __shared__ int ALo[64][33];
    __shared__ int AHi[64][33];
    __shared__ int Bc[64][33];
    __shared__ unsigned char nibS[64][16];
    __shared__ unsigned char nibM[64][16];

    const int* simLoW = (const int*)g_simLo;
    const int* simHiW = (const int*)g_simHi;
    const int* cbW = (const int*)g_cbT8;

    int tx = threadIdx.x & 15;    // d group
    int ty = threadIdx.x >> 4;    // b group

    int accL[4][4];
    int accH[4][4];
    #pragma unroll
    for (int i = 0; i < 4; i++)
        #pragma unroll
        for (int j = 0; j < 4; j++) { accL[i][j] = 0; accH[i][j] = 0; }

    for (int w0 = 0; w0 < 64; w0 += 32) {
        for (int e = threadIdx.x; e < 2048; e += 256) {
            int r = e >> 5;
            int c = e & 31;
            size_t a = ((size_t)(b0 + r) * FDIM + f) * 64 + w0 + c;
            ALo[r][c] = simLoW[a];
            AHi[r][c] = simHiW[a];
            Bc[r][c] = cbW[((size_t)f * DDIM + d0 + r) * 64 + w0 + c];
        }
        __syncthreads();
        #pragma unroll
        for (int w = 0; w < 32; w++) {
            int al[4], ah[4], bb[4];
            #pragma unroll
            for (int i = 0; i < 4; i++) {
                al[i] = ALo[ty * 4 + i][w];
                ah[i] = AHi[ty * 4 + i][w];
            }
            #pragma unroll
            for (int j = 0; j < 4; j++) bb[j] = Bc[tx * 4 + j][w];
            #pragma unroll
            for (int i = 0; i < 4; i++)
                #pragma unroll
                for (int j = 0; j < 4; j++) {
                    accL[i][j] = __dp4a(al[i], bb[j], accL[i][j]);
                    accH[i][j] = __dp4a(ah[i], bb[j], accH[i][j]);
                }
        }
        __syncthreads();
    }

    // stage ternary signs as nibbles (bit j <-> d = d0 + tx*4 + j)
    #pragma unroll
    for (int i = 0; i < 4; i++) {
        unsigned sn = 0, mn = 0;
        #pragma unroll
        for (int j = 0; j < 4; j++) {
            int out = accL[i][j] + (accH[i][j] << 7);
            if (out < 0) sn |= (1u << j);
            if (out != 0) mn |= (1u << j);
        }
        nibS[ty * 4 + i][tx] = (unsigned char)sn;
        nibM[ty * 4 + i][tx] = (unsigned char)mn;
    }
    __syncthreads();

    // assemble words, compare with old packed est, write
    int t = threadIdx.x;
    int ldiff = 0;
    if (t < 128) {
        int bl = t >> 1;          // 0..63
        int wsel = t & 1;         // word within the 64-d tile
        unsigned ws = 0, wm = 0;
        #pragma unroll
        for (int n = 0; n < 8; n++) {
            ws |= (unsigned)nibS[bl][wsel * 8 + n] << (4 * n);
            wm |= (unsigned)nibM[bl][wsel * 8 + n] << (4 * n);
        }
        size_t o = ((size_t)(b0 + bl) * FDIM + f) * WDIM + (d0 >> 5) + wsel;
        unsigned os = g_eS[o];
        unsigned om = g_eM[o];
        if (ws != os || wm != om) ldiff = 1;
        g_eS[o] = ws;
        g_eM[o] = wm;
    }
    if (ldiff) g_diff = 1;
}

// ---------------------------------------------------------------------------
__global__ void step_kernel() {
    if (g_done) return;
    g_k = g_k + 1;
    if (g_diff == 0) g_done = 1;
    g_diff = 0;
}

// ---------------------------------------------------------------------------
// argmax over m (first-index tie-break) + write k.  Output dtype: float32.
// ---------------------------------------------------------------------------
__global__ void argmax_kernel(float* __restrict__ out, int out_size) {
    int gtid = blockIdx.x * blockDim.x + threadIdx.x;
    int w = gtid >> 5;
    int lane = gtid & 31;
    if (w < BDIM * FDIM) {
        const float* srow = g_sim + (size_t)w * MDIM;
        float bv = -3.0e38f;
        int bi = 0;
        for (int m = lane; m < MDIM; m += 32) {
            float v = srow[m];
            if (v > bv) { bv = v; bi = m; }
        }
        for (int off = 16; off > 0; off >>= 1) {
            float ov = __shfl_down_sync(0xffffffffu, bv, off);
            int oi = __shfl_down_sync(0xffffffffu, bi, off);
            if (ov > bv || (ov == bv && oi < bi)) { bv = ov; bi = oi; }
        }
        if (lane == 0) out[w] = (float)bi;
    }
    if (gtid == 0 && out_size > BDIM * FDIM) out[BDIM * FDIM] = (float)g_k;
}

// ---------------------------------------------------------------------------
extern "C" void kernel_launch(void* const* d_in, const int* in_sizes, int n_in,
                              void* d_out, int out_size) {
    const float* inp;
    const float* cb;
    if (in_sizes[0] < in_sizes[1]) { inp = (const float*)d_in[0]; cb = (const float*)d_in[1]; }
    else                           { inp = (const float*)d_in[1]; cb = (const float*)d_in[0]; }
    float* out = (float*)d_out;

    init_est_kernel<<<(FDIM * DDIM + 255) / 256, 256>>>(cb);
    pack_cb_kernel<<<(FDIM * MDIM * DDIM) / 256, 256>>>(cb);
    pack_inp_kernel<<<(BDIM * DDIM) / 256, 256>>>(inp);
    cb_t8_kernel<<<dim3(DDIM / 32, MDIM / 32, FDIM), 256>>>(cb);

    // ---- stage 0 (float path: new_est values are large, not ternary) ----
    zero_sim_kernel<<<(BDIM * FDIM * MDIM) / 256, 256>>>();
    newest_f32_kernel<<<(BDIM * DDIM) / 256, 256>>>(inp);
    gemm1_f32_kernel<<<dim3(16, FDIM, 8), 256>>>(cb);
    gemm2_f32_kernel<<<dim3(DDIM / 64, BDIM / 64, FDIM), 256>>>(cb);
    step_kernel<<<1, 1>>>();
    est_pack_kernel<<<(BDIM * FDIM * DDIM) / 256, 256>>>();

    // ---- stages 1..9 (fully packed path) ----
    for (int it = 1; it < NITERS; it++) {
        newest_bits_kernel<<<(BDIM * WDIM) / 256, 256>>>();
        gemm1_packed_kernel<<<dim3(BDIM / 32, MDIM / 32, FDIM), 256>>>(0, 1);
        gemm2_dp4a_kernel<<<dim3(DDIM / 64, BDIM / 64, FDIM), 256>>>();
        step_kernel<<<1, 1>>>();
    }

    // ---- final similarity from converged packed est, argmax + k ----
    gemm1_packed_kernel<<<dim3(BDIM / 32, MDIM / 32, FDIM), 256>>>(1, 0);
    argmax_kernel<<<(BDIM * FDIM * 32) / 256, 256>>>(out, out_size);
}

// round 9
// speedup vs baseline: 1.2405x; 1.2405x over previous
#include <cuda_runtime.h>
#include <cstdint>

#define BDIM 256
#define FDIM 4
#define MDIM 256
#define DDIM 8192
#define WDIM 256          // DDIM/32 packed words
#define NITERS 10

// Scratch (device globals -- allocation is forbidden)
__device__ float g_sim[BDIM * FDIM * MDIM];       // 1 MB
__device__ float g_colsum[FDIM * DDIM];           // stage-0 est (b-independent)
__device__ float g_P[FDIM * DDIM];                // prod of other 3 colsums
__device__ unsigned g_pS[BDIM * FDIM * WDIM];     // packed new_est sign bits
__device__ unsigned g_pM[BDIM * FDIM * WDIM];     // packed new_est nonzero mask
__device__ unsigned g_eS[BDIM * FDIM * WDIM];     // packed est sign bits (canonical S&M)
__device__ unsigned g_eM[BDIM * FDIM * WDIM];     // packed est nonzero mask
__device__ unsigned g_iS[BDIM * WDIM];            // packed inp sign bits
__device__ unsigned g_cbSt[FDIM * WDIM * MDIM];   // cb sign bits transposed [f][w][m]
__device__ signed char g_cbT8[FDIM * DDIM * MDIM];// cb int8 transposed [f][d][m]
__device__ signed char g_simLo[BDIM * FDIM * MDIM];   // sim = 128*hi + lo
__device__ signed char g_simHi[BDIM * FDIM * MDIM];
__device__ int g_done;
__device__ int g_diff;
__device__ int g_k;

// ---------------------------------------------------------------------------
// colsum[f,d] = sum_m cb[f,m,d]  (coalesced float4 over d), reset flags
// ---------------------------------------------------------------------------
__global__ void colsum_kernel(const float* __restrict__ cb) {
    if (blockIdx.x == 0 && blockIdx.y == 0 && threadIdx.x == 0) {
        g_done = 0; g_diff = 0; g_k = 0;
    }
    int f = blockIdx.y;
    int d = blockIdx.x * 1024 + threadIdx.x * 4;
    float4 s = make_float4(0.f, 0.f, 0.f, 0.f);
    for (int m = 0; m < MDIM; m++) {
        float4 v = *(const float4*)&cb[((size_t)f * MDIM + m) * DDIM + d];
        s.x += v.x; s.y += v.y; s.z += v.z; s.w += v.w;
    }
    *(float4*)&g_colsum[(size_t)f * DDIM + d] = s;
}

// ---------------------------------------------------------------------------
// P_f(d) = product of the other three colsums (exact: integers <= 2^24)
// ---------------------------------------------------------------------------
__global__ void pfactor_kernel() {
    int d = blockIdx.x * blockDim.x + threadIdx.x;
    if (d >= DDIM) return;
    float c0 = g_colsum[d];
    float c1 = g_colsum[DDIM + d];
    float c2 = g_colsum[2 * DDIM + d];
    float c3 = g_colsum[3 * DDIM + d];
    g_P[d]            = (c1 * c2) * c3;
    g_P[DDIM + d]     = (c0 * c2) * c3;
    g_P[2 * DDIM + d] = (c0 * c1) * c3;
    g_P[3 * DDIM + d] = (c0 * c1) * c2;
}

// ---------------------------------------------------------------------------
// pack cb sign bits: g_cbSt[f][w][m]
// ---------------------------------------------------------------------------
__global__ void pack_cb_kernel(const float* __restrict__ cb) {
    int idx = blockIdx.x * blockDim.x + threadIdx.x;  // (f*M+m)*8192 + d
    float v = cb[idx];
    unsigned neg = __ballot_sync(0xffffffffu, v < 0.f);
    if ((threadIdx.x & 31) == 0) {
        int fm = idx >> 13;
        int d = idx & (DDIM - 1);
        int f = fm >> 8;
        int m = fm & 255;
        g_cbSt[((size_t)f * WDIM + (d >> 5)) * MDIM + m] = neg;
    }
}

// ---------------------------------------------------------------------------
__global__ void pack_inp_kernel(const float* __restrict__ inp) {
    int idx = blockIdx.x * blockDim.x + threadIdx.x;  // b*8192 + d
    unsigned neg = __ballot_sync(0xffffffffu, inp[idx] < 0.f);
    if ((threadIdx.x & 31) == 0) {
        int b = idx >> 13;
        int d = idx & (DDIM - 1);
        g_iS[(size_t)b * WDIM + (d >> 5)] = neg;
    }
}

// ---------------------------------------------------------------------------
// cb -> int8 transposed [f][d][m]
// ---------------------------------------------------------------------------
__global__ void cb_t8_kernel(const float* __restrict__ cb) {
    __shared__ signed char t[32][33];
    int d0 = blockIdx.x * 32;
    int m0 = blockIdx.y * 32;
    int f = blockIdx.z;
    int tx = threadIdx.x & 31;
    int ty = threadIdx.x >> 5;
    for (int k = 0; k < 4; k++) {
        int m = m0 + ty * 4 + k;
        t[ty * 4 + k][tx] = (signed char)cb[((size_t)f * MDIM + m) * DDIM + d0 + tx];
    }
    __syncthreads();
    for (int k = 0; k < 4; k++) {
        int d = d0 + ty * 4 + k;
        g_cbT8[((size_t)f * DDIM + d) * MDIM + m0 + tx] = t[tx][ty * 4 + k];
    }
}

// ---------------------------------------------------------------------------
__global__ void zero_sim_kernel() {
    int idx = blockIdx.x * blockDim.x + threadIdx.x;
    if (idx < BDIM * FDIM * MDIM) g_sim[idx] = 0.f;
}

// ---------------------------------------------------------------------------
// stage-0 GEMM1 (float, split-K=8 atomicAdd), A built on the fly:
// A[b,f,d] = inp[b,d] * P_f(d)   (exact; identical values to reference)
// ---------------------------------------------------------------------------
__global__ void gemm1_f32_kernel(const float* __restrict__ cb,
                                 const float* __restrict__ inp) {
    if (g_done) return;
    int bt = blockIdx.x >> 2;
    int mt = blockIdx.x & 3;
    int f = blockIdx.y;
    int b0 = bt * 64;
    int m0 = mt * 64;
    int k0 = blockIdx.z * (DDIM / 8);

    __shared__ float As[32][68];
    __shared__ float Bs[32][68];

    int tx = threadIdx.x & 15;
    int ty = threadIdx.x >> 4;

    float acc[4][4];
    for (int i = 0; i < 4; i++)
        for (int j = 0; j < 4; j++) acc[i][j] = 0.f;

    for (int kk = 0; kk < DDIM / 8; kk += 32) {
        for (int e = threadIdx.x; e < 2048; e += 256) {
            int r = e >> 5;
            int c = e & 31;
            int d = k0 + kk + c;
            As[c][r] = inp[(size_t)(b0 + r) * DDIM + d] * g_P[(size_t)f * DDIM + d];
            Bs[c][r] = cb[((size_t)f * MDIM + m0 + r) * DDIM + d];
        }
        __syncthreads();
        #pragma unroll
        for (int k = 0; k < 32; k++) {
            float a0 = As[k][tx * 4 + 0];
            float a1 = As[k][tx * 4 + 1];
            float a2 = As[k][tx * 4 + 2];
            float a3 = As[k][tx * 4 + 3];
            float c0 = Bs[k][ty * 4 + 0];
            float c1 = Bs[k][ty * 4 + 1];
            float c2 = Bs[k][ty * 4 + 2];
            float c3 = Bs[k][ty * 4 + 3];
            acc[0][0] += a0 * c0; acc[0][1] += a0 * c1; acc[0][2] += a0 * c2; acc[0][3] += a0 * c3;
            acc[1][0] += a1 * c0; acc[1][1] += a1 * c1; acc[1][2] += a1 * c2; acc[1][3] += a1 * c3;
            acc[2][0] += a2 * c0; acc[2][1] += a2 * c1; acc[2][2] += a2 * c2; acc[2][3] += a2 * c3;
            acc[3][0] += a3 * c0; acc[3][1] += a3 * c1; acc[3][2] += a3 * c2; acc[3][3] += a3 * c3;
        }
        __syncthreads();
    }
    for (int i = 0; i < 4; i++)
        for (int j = 0; j < 4; j++) {
            int b = b0 + tx * 4 + i;
            int m = m0 + ty * 4 + j;
            atomicAdd(&g_sim[((size_t)b * FDIM + f) * MDIM + m], acc[i][j]);
        }
}

// ---------------------------------------------------------------------------
// stage-0 GEMM2 (float) + sign + convergence (vs colsum) + PACKED est write
// ---------------------------------------------------------------------------
__global__ void gemm2_f32_kernel(const float* __restrict__ cb) {
    if (g_done) return;
    int f = blockIdx.z;
    int b0 = blockIdx.y * 64;
    int d0 = blockIdx.x * 64;

    __shared__ float As[32][68];
    __shared__ float Bs[32][68];
    __shared__ unsigned char nibS[64][16];
    __shared__ unsigned char nibM[64][16];

    int tx = threadIdx.x & 15;      // d-group
    int ty = threadIdx.x >> 4;      // b-group

    float acc[4][4];
    for (int i = 0; i < 4; i++)
        for (int j = 0; j < 4; j++) acc[i][j] = 0.f;

    for (int mb = 0; mb < MDIM; mb += 32) {
        for (int e = threadIdx.x; e < 2048; e += 256) {
            int r = e >> 5;
            int c = e & 31;
            As[c][r] = g_sim[((size_t)(b0 + r) * FDIM + f) * MDIM + mb + c];
        }
        for (int e = threadIdx.x; e < 2048; e += 256) {
            int m = e >> 6;
            int dd = e & 63;
            Bs[m][dd] = cb[((size_t)f * MDIM + mb + m) * DDIM + d0 + dd];
        }
        __syncthreads();
        #pragma unroll
        for (int m = 0; m < 32; m++) {
            float a0 = As[m][ty * 4 + 0];
            float a1 = As[m][ty * 4 + 1];
            float a2 = As[m][ty * 4 + 2];
            float a3 = As[m][ty * 4 + 3];
            float c0 = Bs[m][tx * 4 + 0];
            float c1 = Bs[m][tx * 4 + 1];
            float c2 = Bs[m][tx * 4 + 2];
            float c3 = Bs[m][tx * 4 + 3];
            acc[0][0] += a0 * c0; acc[0][1] += a0 * c1; acc[0][2] += a0 * c2; acc[0][3] += a0 * c3;
            acc[1][0] += a1 * c0; acc[1][1] += a1 * c1; acc[1][2] += a1 * c2; acc[1][3] += a1 * c3;
            acc[2][0] += a2 * c0; acc[2][1] += a2 * c1; acc[2][2] += a2 * c2; acc[2][3] += a2 * c3;
            acc[3][0] += a3 * c0; acc[3][1] += a3 * c1; acc[3][2] += a3 * c2; acc[3][3] += a3 * c3;
        }
        __syncthreads();
    }

    int ldiff = 0;
    #pragma unroll
    for (int i = 0; i < 4; i++) {
        unsigned sn = 0, mn = 0;
        #pragma unroll
        for (int j = 0; j < 4; j++) {
            float v = acc[i][j];
            float s = (v > 0.f) ? 1.f : ((v < 0.f) ? -1.f : 0.f);
            int d = d0 + tx * 4 + j;
            if (s != g_colsum[(size_t)f * DDIM + d]) ldiff = 1;
            if (v < 0.f) sn |= (1u << j);
            if (v != 0.f) mn |= (1u << j);
        }
        nibS[ty * 4 + i][tx] = (unsigned char)sn;
        nibM[ty * 4 + i][tx] = (unsigned char)mn;
    }
    __syncthreads();

    int t = threadIdx.x;
    if (t < 128) {
        int bl = t >> 1;
        int wsel = t & 1;
        unsigned ws = 0, wm = 0;
        #pragma unroll
        for (int n = 0; n < 8; n++) {
            ws |= (unsigned)nibS[bl][wsel * 8 + n] << (4 * n);
            wm |= (unsigned)nibM[bl][wsel * 8 + n] << (4 * n);
        }
        size_t o = ((size_t)(b0 + bl) * FDIM + f) * WDIM + (d0 >> 5) + wsel;
        g_eS[o] = ws;
        g_eM[o] = wm;
    }
    if (ldiff) g_diff = 1;
}

// ---------------------------------------------------------------------------
// stages >= 1: fully bitwise new_est from packed est + packed inp.
// ---------------------------------------------------------------------------
__global__ void newest_bits_kernel() {
    if (g_done) return;
    int idx = blockIdx.x * blockDim.x + threadIdx.x;   // b*WDIM + w
    if (idx >= BDIM * WDIM) return;
    int b = idx >> 8;
    int w = idx & 255;
    size_t base = (size_t)b * FDIM * WDIM + w;
    unsigned s0 = g_eS[base];
    unsigned s1 = g_eS[base + WDIM];
    unsigned s2 = g_eS[base + 2 * WDIM];
    unsigned s3 = g_eS[base + 3 * WDIM];
    unsigned m0 = g_eM[base];
    unsigned m1 = g_eM[base + WDIM];
    unsigned m2 = g_eM[base + 2 * WDIM];
    unsigned m3 = g_eM[base + 3 * WDIM];
    unsigned is = g_iS[(size_t)b * WDIM + w];
    unsigned sAll = is ^ s0 ^ s1 ^ s2 ^ s3;
    unsigned M0 = m1 & m2 & m3;
    unsigned M1 = m0 & m2 & m3;
    unsigned M2 = m0 & m1 & m3;
    unsigned M3 = m0 & m1 & m2;
    g_pS[base]            = (sAll ^ s0) & M0;
    g_pS[base + WDIM]     = (sAll ^ s1) & M1;
    g_pS[base + 2 * WDIM] = (sAll ^ s2) & M2;
    g_pS[base + 3 * WDIM] = (sAll ^ s3) & M3;
    g_pM[base]            = M0;
    g_pM[base + WDIM]     = M1;
    g_pM[base + 2 * WDIM] = M2;
    g_pM[base + 3 * WDIM] = M3;
}

// ---------------------------------------------------------------------------
// packed GEMM1: sim = nz - 2*popc((Sa^Sb)&Ma).  Writes f32 sim + int8 planes.
// ---------------------------------------------------------------------------
__global__ void gemm1_packed_kernel(int src_est, int respect_done) {
    if (respect_done && g_done) return;
    const unsigned* PS = src_est ? g_eS : g_pS;
    const unsigned* PM = src_est ? g_eM : g_pM;
    int b0 = blockIdx.x * 32;
    int m0 = blockIdx.y * 32;
    int f = blockIdx.z;

    __shared__ unsigned AS[32][33];
    __shared__ unsigned AM[32][33];
    __shared__ unsigned BS[32][33];

    int tx = threadIdx.x & 15;
    int ty = threadIdx.x >> 4;

    int acc[2][2] = {{0, 0}, {0, 0}};
    int accM[2] = {0, 0};

    for (int w0 = 0; w0 < WDIM; w0 += 32) {
        for (int e = threadIdx.x; e < 1024; e += 256) {
            int r = e >> 5;
            int c = e & 31;
            size_t src = ((size_t)(b0 + r) * FDIM + f) * WDIM + w0 + c;
            AS[c][r] = PS[src];
            AM[c][r] = PM[src];
        }
        for (int e = threadIdx.x; e < 1024; e += 256) {
            int w = e >> 5;
            int m = e & 31;
            BS[w][m] = g_cbSt[((size_t)f * WDIM + w0 + w) * MDIM + m0 + m];
        }
        __syncthreads();
        #pragma unroll
        for (int w = 0; w < 32; w++) {
            unsigned sa0 = AS[w][tx * 2 + 0];
            unsigned sa1 = AS[w][tx * 2 + 1];
            unsigned ma0 = AM[w][tx * 2 + 0];
            unsigned ma1 = AM[w][tx * 2 + 1];
            unsigned sb0 = BS[w][ty * 2 + 0];
            unsigned sb1 = BS[w][ty * 2 + 1];
            accM[0] += __popc(ma0);
            accM[1] += __popc(ma1);
            acc[0][0] += __popc((sa0 ^ sb0) & ma0);
            acc[0][1] += __popc((sa0 ^ sb1) & ma0);
            acc[1][0] += __popc((sa1 ^ sb0) & ma1);
            acc[1][1] += __popc((sa1 ^ sb1) & ma1);
        }
        __syncthreads();
    }

    #pragma unroll
    for (int i = 0; i < 2; i++) {
        int b = b0 + tx * 2 + i;
        #pragma unroll
        for (int j = 0; j < 2; j++) {
            int m = m0 + ty * 2 + j;
            int sim = accM[i] - 2 * acc[i][j];
            size_t o = ((size_t)b * FDIM + f) * MDIM + m;
            g_sim[o] = (float)sim;
            int hi = (sim + 64) >> 7;
            int lo = sim - (hi << 7);
            g_simHi[o] = (signed char)hi;
            g_simLo[o] = (signed char)lo;
        }
    }
}

// ---------------------------------------------------------------------------
// packed GEMM2 via IMMA mma.sync.m16n8k32.s8 (2 planes) + packed epilogue.
// grid (128 dtiles(64), 4 btiles(64), F), block 256 = 8 warps (4b x 2d).
// A-fragment ordering per PTX ISA: a0=(g,k) a1=(g+8,k) a2=(g,k+16) a3=(g+8,k+16).
// ---------------------------------------------------------------------------
__device__ __forceinline__ void imma16832(int& c0, int& c1, int& c2, int& c3,
                                          unsigned a0, unsigned a1, unsigned a2, unsigned a3,
                                          unsigned b0, unsigned b1) {
    asm volatile(
        "mma.sync.aligned.m16n8k32.row.col.s32.s8.s8.s32 "
        "{%0,%1,%2,%3}, {%4,%5,%6,%7}, {%8,%9}, {%0,%1,%2,%3};\n"
        : "+r"(c0), "+r"(c1), "+r"(c2), "+r"(c3)
        : "r"(a0), "r"(a1), "r"(a2), "r"(a3), "r"(b0), "r"(b1));
}

__global__ void gemm2_imma_kernel() {
    if (g_done) return;
    int f = blockIdx.z;
    int d0 = blockIdx.x * 64;
    int b0 = blockIdx.y * 64;
    int w = threadIdx.x >> 5;
    int lane = threadIdx.x & 31;
    int g = lane >> 2;
    int tig = lane & 3;
    int wb = w & 3;          // 4 b-warps
    int wd = w >> 2;         // 2 d-warps

    const unsigned* loW = (const unsigned*)g_simLo;
    const unsigned* hiW = (const unsigned*)g_simHi;
    const unsigned* cbW = (const unsigned*)g_cbT8;

    int accL[4][4];
    int accH[4][4];
    #pragma unroll
    for (int nt = 0; nt < 4; nt++)
        #pragma unroll
        for (int i = 0; i < 4; i++) { accL[nt][i] = 0; accH[nt][i] = 0; }

    int r0 = b0 + wb * 16 + g;       // A rows g / g+8
    size_t aB0 = ((size_t)r0 * FDIM + f) * 64;        // u32 stride: 256 s8 = 64 u32
    size_t aB1 = ((size_t)(r0 + 8) * FDIM + f) * 64;
    size_t dRow = (size_t)f * DDIM + d0 + wd * 32 + g;  // B col base (d)

    #pragma unroll
    for (int kc = 0; kc < 8; kc++) {
        int kw = kc * 8 + tig;       // u32 index of k (k = kc*32 + tig*4)
        // PTX fragment order: a0=(g,k)  a1=(g+8,k)  a2=(g,k+16)  a3=(g+8,k+16)
        unsigned al0 = loW[aB0 + kw];
        unsigned al1 = loW[aB1 + kw];
        unsigned al2 = loW[aB0 + kw + 4];
        unsigned al3 = loW[aB1 + kw + 4];
        unsigned ah0 = hiW[aB0 + kw];
        unsigned ah1 = hiW[aB1 + kw];
        unsigned ah2 = hiW[aB0 + kw + 4];
        unsigned ah3 = hiW[aB1 + kw + 4];
        #pragma unroll
        for (int nt = 0; nt < 4; nt++) {
            size_t bi = (dRow + nt * 8) * 64 + kw;
            unsigned bb0 = cbW[bi];
            unsigned bb1 = cbW[bi + 4];
            imma16832(accL[nt][0], accL[nt][1], accL[nt][2], accL[nt][3],
                      al0, al1, al2, al3, bb0, bb1);
            imma16832(accH[nt][0], accH[nt][1], accH[nt][2], accH[nt][3],
                      ah0, ah1, ah2, ah3, bb0, bb1);
        }
    }

    // epilogue: out = accL + (accH << 7); sign/mask bytes -> packed words
    __shared__ unsigned char sB[64][64];   // bit0 = sign, bit1 = nonzero
    int bl0 = wb * 16 + g;
    int bl1 = bl0 + 8;
    #pragma unroll
    for (int nt = 0; nt < 4; nt++) {
        int dc = wd * 32 + nt * 8 + tig * 2;
        int o00 = accL[nt][0] + (accH[nt][0] << 7);
        int o01 = accL[nt][1] + (accH[nt][1] << 7);
        int o10 = accL[nt][2] + (accH[nt][2] << 7);
        int o11 = accL[nt][3] + (accH[nt][3] << 7);
        sB[bl0][dc]     = (unsigned char)((o00 < 0 ? 1u : 0u) | (o00 != 0 ? 2u : 0u));
        sB[bl0][dc + 1] = (unsigned char)((o01 < 0 ? 1u : 0u) | (o01 != 0 ? 2u : 0u));
        sB[bl1][dc]     = (unsigned char)((o10 < 0 ? 1u : 0u) | (o10 != 0 ? 2u : 0u));
        sB[bl1][dc + 1] = (unsigned char)((o11 < 0 ? 1u : 0u) | (o11 != 0 ? 2u : 0u));
    }
    __syncthreads();

    int ldiff = 0;
    int t = threadIdx.x;
    if (t < 128) {
        int bl = t >> 1;
        int wsel = t & 1;
        unsigned ws = 0, wm = 0;
        #pragma unroll
        for (int n = 0; n < 32; n++) {
            unsigned byte = sB[bl][wsel * 32 + n];
            ws |= (byte & 1u) << n;
            wm |= ((byte >> 1) & 1u) << n;
        }
        size_t o = ((size_t)(b0 + bl) * FDIM + f) * WDIM + (d0 >> 5) + wsel;
        if (ws != g_eS[o] || wm != g_eM[o]) ldiff = 1;
        g_eS[o] = ws;
        g_eM[o] = wm;
    }
    if (ldiff) g_diff = 1;
}

// ---------------------------------------------------------------------------
__global__ void step_kernel() {
    if (g_done) return;
    g_k = g_k + 1;
    if (g_diff == 0) g_done = 1;
    g_diff = 0;
}

// ---------------------------------------------------------------------------
// argmax over m (first-index tie-break) + write k.  Output dtype: float32.
// ---------------------------------------------------------------------------
__global__ void argmax_kernel(float* __restrict__ out, int out_size) {
    int gtid = blockIdx.x * blockDim.x + threadIdx.x;
    int w = gtid >> 5;
    int lane = gtid & 31;
    if (w < BDIM * FDIM) {
        const float* srow = g_sim + (size_t)w * MDIM;
        float bv = -3.0e38f;
        int bi = 0;
        for (int m = lane; m < MDIM; m += 32) {
            float v = srow[m];
            if (v > bv) { bv = v; bi = m; }
        }
        for (int off = 16; off > 0; off >>= 1) {
            float ov = __shfl_down_sync(0xffffffffu, bv, off);
            int oi = __shfl_down_sync(0xffffffffu, bi, off);
            if (ov > bv || (ov == bv && oi < bi)) { bv = ov; bi = oi; }
        }
        if (lane == 0) out[w] = (float)bi;
    }
    if (gtid == 0 && out_size > BDIM * FDIM) out[BDIM * FDIM] = (float)g_k;
}

// ---------------------------------------------------------------------------
extern "C" void kernel_launch(void* const* d_in, const int* in_sizes, int n_in,
                              void* d_out, int out_size) {
    const float* inp;
    const float* cb;
    if (in_sizes[0] < in_sizes[1]) { inp = (const float*)d_in[0]; cb = (const float*)d_in[1]; }
    else                           { inp = (const float*)d_in[1]; cb = (const float*)d_in[0]; }
    float* out = (float*)d_out;

    colsum_kernel<<<dim3(8, FDIM), 256>>>(cb);
    pfactor_kernel<<<DDIM / 256, 256>>>();
    pack_cb_kernel<<<(FDIM * MDIM * DDIM) / 256, 256>>>(cb);
    pack_inp_kernel<<<(BDIM * DDIM) / 256, 256>>>(inp);
    cb_t8_kernel<<<dim3(DDIM / 32, MDIM / 32, FDIM), 256>>>(cb);

    // ---- stage 0 (float path; A = inp * P built on the fly) ----
    zero_sim_kernel<<<(BDIM * FDIM * MDIM) / 256, 256>>>();
    gemm1_f32_kernel<<<dim3(16, FDIM, 8), 256>>>(cb, inp);
    gemm2_f32_kernel<<<dim3(DDIM / 64, BDIM / 64, FDIM), 256>>>(cb);
    step_kernel<<<1, 1>>>();

    // ---- stages 1..9 (packed + IMMA path) ----
    for (int it = 1; it < NITERS; it++) {
        newest_bits_kernel<<<(BDIM * WDIM) / 256, 256>>>();
        gemm1_packed_kernel<<<dim3(BDIM / 32, MDIM / 32, FDIM), 256>>>(0, 1);
        gemm2_imma_kernel<<<dim3(DDIM / 64, BDIM / 64, FDIM), 256>>>();
        step_kernel<<<1, 1>>>();
    }

    // ---- final similarity from converged packed est, argmax + k ----
    gemm1_packed_kernel<<<dim3(BDIM / 32, MDIM / 32, FDIM), 256>>>(1, 0);
    argmax_kernel<<<(BDIM * FDIM * 32) / 256, 256>>>(out, out_size);
}

// round 10
// speedup vs baseline: 1.3359x; 1.0770x over previous
#include <cuda_runtime.h>
#include <cstdint>

#define BDIM 256
#define FDIM 4
#define MDIM 256
#define DDIM 8192
#define WDIM 256          // DDIM/32 packed words
#define NITERS 10

// Scratch (device globals -- allocation is forbidden)
__device__ float g_sim[BDIM * FDIM * MDIM];       // 1 MB
__device__ float g_colsum[FDIM * DDIM];           // stage-0 est (b-independent)
__device__ float g_P[FDIM * DDIM];                // prod of other 3 colsums
__device__ unsigned g_pS[BDIM * FDIM * WDIM];     // packed new_est sign bits
__device__ unsigned g_pM[BDIM * FDIM * WDIM];     // packed new_est nonzero mask
__device__ unsigned g_eS[BDIM * FDIM * WDIM];     // packed est sign bits (canonical S&M)
__device__ unsigned g_eM[BDIM * FDIM * WDIM];     // packed est nonzero mask
__device__ unsigned g_iS[BDIM * WDIM];            // packed inp sign bits
__device__ unsigned g_cbSt[FDIM * WDIM * MDIM];   // cb sign bits transposed [f][w][m]
// IMMA operands in warp-LDG-linear fragment order:
__device__ unsigned g_simLoP[(BDIM / 16) * FDIM * 1024]; // A tiles: 16 b-rows x 256 k, 4KB each
__device__ unsigned g_simHiP[(BDIM / 16) * FDIM * 1024];
__device__ unsigned g_cbP[(DDIM / 32) * FDIM * 2048];    // B tiles: 32 d-rows x 256 k, 8KB each
__device__ int g_done;
__device__ int g_diff;
__device__ int g_k;

// ---------------------------------------------------------------------------
// colsum[f,d] = sum_m cb[f,m,d]; reset flags
// ---------------------------------------------------------------------------
__global__ void colsum_kernel(const float* __restrict__ cb) {
    if (blockIdx.x == 0 && blockIdx.y == 0 && threadIdx.x == 0) {
        g_done = 0; g_diff = 0; g_k = 0;
    }
    int f = blockIdx.y;
    int d = blockIdx.x * 1024 + threadIdx.x * 4;
    float4 s = make_float4(0.f, 0.f, 0.f, 0.f);
    for (int m = 0; m < MDIM; m++) {
        float4 v = *(const float4*)&cb[((size_t)f * MDIM + m) * DDIM + d];
        s.x += v.x; s.y += v.y; s.z += v.z; s.w += v.w;
    }
    *(float4*)&g_colsum[(size_t)f * DDIM + d] = s;
}

// ---------------------------------------------------------------------------
__global__ void pfactor_kernel() {
    int d = blockIdx.x * blockDim.x + threadIdx.x;
    if (d >= DDIM) return;
    float c0 = g_colsum[d];
    float c1 = g_colsum[DDIM + d];
    float c2 = g_colsum[2 * DDIM + d];
    float c3 = g_colsum[3 * DDIM + d];
    g_P[d]            = (c1 * c2) * c3;
    g_P[DDIM + d]     = (c0 * c2) * c3;
    g_P[2 * DDIM + d] = (c0 * c1) * c3;
    g_P[3 * DDIM + d] = (c0 * c1) * c2;
}

// ---------------------------------------------------------------------------
__global__ void pack_cb_kernel(const float* __restrict__ cb) {
    int idx = blockIdx.x * blockDim.x + threadIdx.x;  // (f*M+m)*8192 + d
    float v = cb[idx];
    unsigned neg = __ballot_sync(0xffffffffu, v < 0.f);
    if ((threadIdx.x & 31) == 0) {
        int fm = idx >> 13;
        int d = idx & (DDIM - 1);
        int f = fm >> 8;
        int m = fm & 255;
        g_cbSt[((size_t)f * WDIM + (d >> 5)) * MDIM + m] = neg;
    }
}

// ---------------------------------------------------------------------------
__global__ void pack_inp_kernel(const float* __restrict__ inp) {
    int idx = blockIdx.x * blockDim.x + threadIdx.x;  // b*8192 + d
    unsigned neg = __ballot_sync(0xffffffffu, inp[idx] < 0.f);
    if ((threadIdx.x & 31) == 0) {
        int b = idx >> 13;
        int d = idx & (DDIM - 1);
        g_iS[(size_t)b * WDIM + (d >> 5)] = neg;
    }
}

// ---------------------------------------------------------------------------
// cb -> int8, B-operand tiles in warp-LDG-linear fragment order.
// Tile = 32 d-rows x 256 m(k) = 2048 u32.  grid (D/32, F), block 256.
// Stored u32 index inside tile: ((nt*4+q)*32 + g*4 + tig)*4 + rem, where
//   d_local = nt*8+g,  m-word w = tig + 4*(4q+rem)
// ---------------------------------------------------------------------------
__global__ void cb_permute_kernel(const float* __restrict__ cb) {
    __shared__ signed char t[32][260];
    int d0 = blockIdx.x * 32;
    int f = blockIdx.y;
    for (int idx = threadIdx.x; idx < 256 * 32; idx += 256) {
        int m = idx >> 5;
        int dl = idx & 31;
        t[dl][m] = (signed char)cb[((size_t)f * MDIM + m) * DDIM + d0 + dl];
    }
    __syncthreads();
    unsigned tile = (unsigned)(blockIdx.x * FDIM + f) * 2048;
    for (int widx = threadIdx.x; widx < 2048; widx += 256) {
        int dl = widx >> 6;
        int w = widx & 63;
        unsigned v = (unsigned)(unsigned char)t[dl][4 * w]
                   | ((unsigned)(unsigned char)t[dl][4 * w + 1] << 8)
                   | ((unsigned)(unsigned char)t[dl][4 * w + 2] << 16)
                   | ((unsigned)(unsigned char)t[dl][4 * w + 3] << 24);
        int nt = dl >> 3, g = dl & 7;
        int tig = w & 3, i = w >> 2, q = i >> 2, rem = i & 3;
        g_cbP[tile + (unsigned)(((nt * 4 + q) * 32 + g * 4 + tig) * 4 + rem)] = v;
    }
}

// ---------------------------------------------------------------------------
__global__ void zero_sim_kernel() {
    int idx = blockIdx.x * blockDim.x + threadIdx.x;
    if (idx < BDIM * FDIM * MDIM) g_sim[idx] = 0.f;
}

// ---------------------------------------------------------------------------
// stage-0 GEMM1 (float, split-K=8 atomicAdd), A = inp * P on the fly
// ---------------------------------------------------------------------------
__global__ void gemm1_f32_kernel(const float* __restrict__ cb,
                                 const float* __restrict__ inp) {
    if (g_done) return;
    int bt = blockIdx.x >> 2;
    int mt = blockIdx.x & 3;
    int f = blockIdx.y;
    int b0 = bt * 64;
    int m0 = mt * 64;
    int k0 = blockIdx.z * (DDIM / 8);

    __shared__ float As[32][68];
    __shared__ float Bs[32][68];

    int tx = threadIdx.x & 15;
    int ty = threadIdx.x >> 4;

    float acc[4][4];
    for (int i = 0; i < 4; i++)
        for (int j = 0; j < 4; j++) acc[i][j] = 0.f;

    for (int kk = 0; kk < DDIM / 8; kk += 32) {
        for (int e = threadIdx.x; e < 2048; e += 256) {
            int r = e >> 5;
            int c = e & 31;
            int d = k0 + kk + c;
            As[c][r] = inp[(size_t)(b0 + r) * DDIM + d] * g_P[(size_t)f * DDIM + d];
            Bs[c][r] = cb[((size_t)f * MDIM + m0 + r) * DDIM + d];
        }
        __syncthreads();
        #pragma unroll
        for (int k = 0; k < 32; k++) {
            float a0 = As[k][tx * 4 + 0];
            float a1 = As[k][tx * 4 + 1];
            float a2 = As[k][tx * 4 + 2];
            float a3 = As[k][tx * 4 + 3];
            float c0 = Bs[k][ty * 4 + 0];
            float c1 = Bs[k][ty * 4 + 1];
            float c2 = Bs[k][ty * 4 + 2];
            float c3 = Bs[k][ty * 4 + 3];
            acc[0][0] += a0 * c0; acc[0][1] += a0 * c1; acc[0][2] += a0 * c2; acc[0][3] += a0 * c3;
            acc[1][0] += a1 * c0; acc[1][1] += a1 * c1; acc[1][2] += a1 * c2; acc[1][3] += a1 * c3;
            acc[2][0] += a2 * c0; acc[2][1] += a2 * c1; acc[2][2] += a2 * c2; acc[2][3] += a2 * c3;
            acc[3][0] += a3 * c0; acc[3][1] += a3 * c1; acc[3][2] += a3 * c2; acc[3][3] += a3 * c3;
        }
        __syncthreads();
    }
    for (int i = 0; i < 4; i++)
        for (int j = 0; j < 4; j++) {
            int b = b0 + tx * 4 + i;
            int m = m0 + ty * 4 + j;
            atomicAdd(&g_sim[((size_t)b * FDIM + f) * MDIM + m], acc[i][j]);
        }
}

// ---------------------------------------------------------------------------
// stage-0 GEMM2 (float) + sign + convergence (vs colsum) + PACKED est write
// ---------------------------------------------------------------------------
__global__ void gemm2_f32_kernel(const float* __restrict__ cb) {
    if (g_done) return;
    int f = blockIdx.z;
    int b0 = blockIdx.y * 64;
    int d0 = blockIdx.x * 64;

    __shared__ float As[32][68];
    __shared__ float Bs[32][68];
    __shared__ unsigned char nibS[64][16];
    __shared__ unsigned char nibM[64][16];

    int tx = threadIdx.x & 15;      // d-group
    int ty = threadIdx.x >> 4;      // b-group

    float acc[4][4];
    for (int i = 0; i < 4; i++)
        for (int j = 0; j < 4; j++) acc[i][j] = 0.f;

    for (int mb = 0; mb < MDIM; mb += 32) {
        for (int e = threadIdx.x; e < 2048; e += 256) {
            int r = e >> 5;
            int c = e & 31;
            As[c][r] = g_sim[((size_t)(b0 + r) * FDIM + f) * MDIM + mb + c];
        }
        for (int e = threadIdx.x; e < 2048; e += 256) {
            int m = e >> 6;
            int dd = e & 63;
            Bs[m][dd] = cb[((size_t)f * MDIM + mb + m) * DDIM + d0 + dd];
        }
        __syncthreads();
        #pragma unroll
        for (int m = 0; m < 32; m++) {
            float a0 = As[m][ty * 4 + 0];
            float a1 = As[m][ty * 4 + 1];
            float a2 = As[m][ty * 4 + 2];
            float a3 = As[m][ty * 4 + 3];
            float c0 = Bs[m][tx * 4 + 0];
            float c1 = Bs[m][tx * 4 + 1];
            float c2 = Bs[m][tx * 4 + 2];
            float c3 = Bs[m][tx * 4 + 3];
            acc[0][0] += a0 * c0; acc[0][1] += a0 * c1; acc[0][2] += a0 * c2; acc[0][3] += a0 * c3;
            acc[1][0] += a1 * c0; acc[1][1] += a1 * c1; acc[1][2] += a1 * c2; acc[1][3] += a1 * c3;
            acc[2][0] += a2 * c0; acc[2][1] += a2 * c1; acc[2][2] += a2 * c2; acc[2][3] += a2 * c3;
            acc[3][0] += a3 * c0; acc[3][1] += a3 * c1; acc[3][2] += a3 * c2; acc[3][3] += a3 * c3;
        }
        __syncthreads();
    }

    int ldiff = 0;
    #pragma unroll
    for (int i = 0; i < 4; i++) {
        unsigned sn = 0, mn = 0;
        #pragma unroll
        for (int j = 0; j < 4; j++) {
            float v = acc[i][j];
            float s = (v > 0.f) ? 1.f : ((v < 0.f) ? -1.f : 0.f);
            int d = d0 + tx * 4 + j;
            if (s != g_colsum[(size_t)f * DDIM + d]) ldiff = 1;
            if (v < 0.f) sn |= (1u << j);
            if (v != 0.f) mn |= (1u << j);
        }
        nibS[ty * 4 + i][tx] = (unsigned char)sn;
        nibM[ty * 4 + i][tx] = (unsigned char)mn;
    }
    __syncthreads();

    int t = threadIdx.x;
    if (t < 128) {
        int bl = t >> 1;
        int wsel = t & 1;
        unsigned ws = 0, wm = 0;
        #pragma unroll
        for (int n = 0; n < 8; n++) {
            ws |= (unsigned)nibS[bl][wsel * 8 + n] << (4 * n);
            wm |= (unsigned)nibM[bl][wsel * 8 + n] << (4 * n);
        }
        size_t o = ((size_t)(b0 + bl) * FDIM + f) * WDIM + (d0 >> 5) + wsel;
        g_eS[o] = ws;
        g_eM[o] = wm;
    }
    if (ldiff) g_diff = 1;
}

// ---------------------------------------------------------------------------
// stages >= 1: fully bitwise new_est from packed est + packed inp.
// ---------------------------------------------------------------------------
__global__ void newest_bits_kernel() {
    if (g_done) return;
    int idx = blockIdx.x * blockDim.x + threadIdx.x;   // b*WDIM + w
    if (idx >= BDIM * WDIM) return;
    int b = idx >> 8;
    int w = idx & 255;
    size_t base = (size_t)b * FDIM * WDIM + w;
    unsigned s0 = g_eS[base];
    unsigned s1 = g_eS[base + WDIM];
    unsigned s2 = g_eS[base + 2 * WDIM];
    unsigned s3 = g_eS[base + 3 * WDIM];
    unsigned m0 = g_eM[base];
    unsigned m1 = g_eM[base + WDIM];
    unsigned m2 = g_eM[base + 2 * WDIM];
    unsigned m3 = g_eM[base + 3 * WDIM];
    unsigned is = g_iS[(size_t)b * WDIM + w];
    unsigned sAll = is ^ s0 ^ s1 ^ s2 ^ s3;
    unsigned M0 = m1 & m2 & m3;
    unsigned M1 = m0 & m2 & m3;
    unsigned M2 = m0 & m1 & m3;
    unsigned M3 = m0 & m1 & m2;
    g_pS[base]            = (sAll ^ s0) & M0;
    g_pS[base + WDIM]     = (sAll ^ s1) & M1;
    g_pS[base + 2 * WDIM] = (sAll ^ s2) & M2;
    g_pS[base + 3 * WDIM] = (sAll ^ s3) & M3;
    g_pM[base]            = M0;
    g_pM[base + WDIM]     = M1;
    g_pM[base + 2 * WDIM] = M2;
    g_pM[base + 3 * WDIM] = M3;
}

// ---------------------------------------------------------------------------
// packed GEMM1: sim = nz - 2*popc((Sa^Sb)&Ma).
// Writes f32 sim + int8 planes in A-fragment-permuted order.
// ---------------------------------------------------------------------------
__global__ void gemm1_packed_kernel(int src_est, int respect_done) {
    if (respect_done && g_done) return;
    const unsigned* PS = src_est ? g_eS : g_pS;
    const unsigned* PM = src_est ? g_eM : g_pM;
    int b0 = blockIdx.x * 32;
    int m0 = blockIdx.y * 32;
    int f = blockIdx.z;

    __shared__ unsigned AS[32][33];
    __shared__ unsigned AM[32][33];
    __shared__ unsigned BS[32][33];

    int tx = threadIdx.x & 15;
    int ty = threadIdx.x >> 4;

    int acc[2][2] = {{0, 0}, {0, 0}};
    int accM[2] = {0, 0};

    for (int w0 = 0; w0 < WDIM; w0 += 32) {
        for (int e = threadIdx.x; e < 1024; e += 256) {
            int r = e >> 5;
            int c = e & 31;
            size_t src = ((size_t)(b0 + r) * FDIM + f) * WDIM + w0 + c;
            AS[c][r] = PS[src];
            AM[c][r] = PM[src];
        }
        for (int e = threadIdx.x; e < 1024; e += 256) {
            int w = e >> 5;
            int m = e & 31;
            BS[w][m] = g_cbSt[((size_t)f * WDIM + w0 + w) * MDIM + m0 + m];
        }
        __syncthreads();
        #pragma unroll
        for (int w = 0; w < 32; w++) {
            unsigned sa0 = AS[w][tx * 2 + 0];
            unsigned sa1 = AS[w][tx * 2 + 1];
            unsigned ma0 = AM[w][tx * 2 + 0];
            unsigned ma1 = AM[w][tx * 2 + 1];
            unsigned sb0 = BS[w][ty * 2 + 0];
            unsigned sb1 = BS[w][ty * 2 + 1];
            accM[0] += __popc(ma0);
            accM[1] += __popc(ma1);
            acc[0][0] += __popc((sa0 ^ sb0) & ma0);
            acc[0][1] += __popc((sa0 ^ sb1) & ma0);
            acc[1][0] += __popc((sa1 ^ sb0) & ma1);
            acc[1][1] += __popc((sa1 ^ sb1) & ma1);
        }
        __syncthreads();
    }

    unsigned char* loB = (unsigned char*)g_simLoP;
    unsigned char* hiB = (unsigned char*)g_simHiP;
    #pragma unroll
    for (int i = 0; i < 2; i++) {
        int b = b0 + tx * 2 + i;
        int tileA = ((b >> 4) * FDIM + f) * 4096;
        int bl = b & 15;
        int gg = bl & 7;
        int half = bl >> 3;
        #pragma unroll
        for (int j = 0; j < 2; j++) {
            int m = m0 + ty * 2 + j;
            int sim = accM[i] - 2 * acc[i][j];
            g_sim[((size_t)b * FDIM + f) * MDIM + m] = (float)sim;
            int hi = (sim + 64) >> 7;
            int lo = sim - (hi << 7);
            int w = m >> 2, tig = w & 3, ii = w >> 2, q = ii >> 2, rem = ii & 3;
            int bidx = tileA + (((half * 4 + q) * 32 + gg * 4 + tig) * 4 + rem) * 4 + (m & 3);
            loB[bidx] = (unsigned char)(signed char)lo;
            hiB[bidx] = (unsigned char)(signed char)hi;
        }
    }
}

// ---------------------------------------------------------------------------
// packed GEMM2 via IMMA with fragment-order operands (all LDG.128, coalesced).
// grid (128 dtiles(64), 4 btiles(64), F), block 256 = 8 warps (4b x 2d).
// ---------------------------------------------------------------------------
__device__ __forceinline__ void imma16832(int& c0, int& c1, int& c2, int& c3,
                                          unsigned a0, unsigned a1, unsigned a2, unsigned a3,
                                          unsigned b0, unsigned b1) {
    asm volatile(
        "mma.sync.aligned.m16n8k32.row.col.s32.s8.s8.s32 "
        "{%0,%1,%2,%3}, {%4,%5,%6,%7}, {%8,%9}, {%0,%1,%2,%3};\n"
        : "+r"(c0), "+r"(c1), "+r"(c2), "+r"(c3)
        : "r"(a0), "r"(a1), "r"(a2), "r"(a3), "r"(b0), "r"(b1));
}

__global__ void gemm2_imma_kernel() {
    if (g_done) return;
    int f = blockIdx.z;
    int d0 = blockIdx.x * 64;
    int b0 = blockIdx.y * 64;
    int w = threadIdx.x >> 5;
    int lane = threadIdx.x & 31;
    int g = lane >> 2;
    int tig = lane & 3;
    int wb = w & 3;          // 4 b-warps
    int wd = w >> 2;         // 2 d-warps

    const uint4* Alo = (const uint4*)g_simLoP;
    const uint4* Ahi = (const uint4*)g_simHiP;
    const uint4* Bp  = (const uint4*)g_cbP;
    unsigned tA = (unsigned)(((b0 >> 4) + wb) * FDIM + f) * 256;   // uint4 units (1024 u32)
    unsigned tB = (unsigned)(((d0 >> 5) + wd) * FDIM + f) * 512;   // uint4 units (2048 u32)

    int accL[4][4];
    int accH[4][4];
    #pragma unroll
    for (int nt = 0; nt < 4; nt++)
        #pragma unroll
        for (int i = 0; i < 4; i++) { accL[nt][i] = 0; accH[nt][i] = 0; }

    #pragma unroll
    for (int q = 0; q < 4; q++) {
        uint4 al0 = Alo[tA + q * 32 + lane];          // half 0 (rows g)
        uint4 al1 = Alo[tA + (4 + q) * 32 + lane];    // half 1 (rows g+8)
        uint4 ah0 = Ahi[tA + q * 32 + lane];
        uint4 ah1 = Ahi[tA + (4 + q) * 32 + lane];
        uint4 bq0 = Bp[tB + (0 * 4 + q) * 32 + lane];
        uint4 bq1 = Bp[tB + (1 * 4 + q) * 32 + lane];
        uint4 bq2 = Bp[tB + (2 * 4 + q) * 32 + lane];
        uint4 bq3 = Bp[tB + (3 * 4 + q) * 32 + lane];
        // s = 0  (kc = 2q):   a0=al0.x a1=al1.x a2=al0.y a3=al1.y ; b = .x,.y
        imma16832(accL[0][0], accL[0][1], accL[0][2], accL[0][3], al0.x, al1.x, al0.y, al1.y, bq0.x, bq0.y);
        imma16832(accL[1][0], accL[1][1], accL[1][2], accL[1][3], al0.x, al1.x, al0.y, al1.y, bq1.x, bq1.y);
        imma16832(accL[2][0], accL[2][1], accL[2][2], accL[2][3], al0.x, al1.x, al0.y, al1.y, bq2.x, bq2.y);
        imma16832(accL[3][0], accL[3][1], accL[3][2], accL[3][3], al0.x, al1.x, al0.y, al1.y, bq3.x, bq3.y);
        imma16832(accH[0][0], accH[0][1], accH[0][2], accH[0][3], ah0.x, ah1.x, ah0.y, ah1.y, bq0.x, bq0.y);
        imma16832(accH[1][0], accH[1][1], accH[1][2], accH[1][3], ah0.x, ah1.x, ah0.y, ah1.y, bq1.x, bq1.y);
        imma16832(accH[2][0], accH[2][1], accH[2][2], accH[2][3], ah0.x, ah1.x, ah0.y, ah1.y, bq2.x, bq2.y);
        imma16832(accH[3][0], accH[3][1], accH[3][2], accH[3][3], ah0.x, ah1.x, ah0.y, ah1.y, bq3.x, bq3.y);
        // s = 1  (kc = 2q+1): a0=al0.z a1=al1.z a2=al0.w a3=al1.w ; b = .z,.w
        imma16832(accL[0][0], accL[0][1], accL[0][2], accL[0][3], al0.z, al1.z, al0.w, al1.w, bq0.z, bq0.w);
        imma16832(accL[1][0], accL[1][1], accL[1][2], accL[1][3], al0.z, al1.z, al0.w, al1.w, bq1.z, bq1.w);
        imma16832(accL[2][0], accL[2][1], accL[2][2], accL[2][3], al0.z, al1.z, al0.w, al1.w, bq2.z, bq2.w);
        imma16832(accL[3][0], accL[3][1], accL[3][2], accL[3][3], al0.z, al1.z, al0.w, al1.w, bq3.z, bq3.w);
        imma16832(accH[0][0], accH[0][1], accH[0][2], accH[0][3], ah0.z, ah1.z, ah0.w, ah1.w, bq0.z, bq0.w);
        imma16832(accH[1][0], accH[1][1], accH[1][2], accH[1][3], ah0.z, ah1.z, ah0.w, ah1.w, bq1.z, bq1.w);
        imma16832(accH[2][0], accH[2][1], accH[2][2], accH[2][3], ah0.z, ah1.z, ah0.w, ah1.w, bq2.z, bq2.w);
        imma16832(accH[3][0], accH[3][1], accH[3][2], accH[3][3], ah0.z, ah1.z, ah0.w, ah1.w, bq3.z, bq3.w);
    }

    // epilogue (proven round 9): out = accL + (accH << 7); pack -> est planes
    __shared__ unsigned char sB[64][64];   // bit0 = sign, bit1 = nonzero
    int bl0 = wb * 16 + g;
    int bl1 = bl0 + 8;
    #pragma unroll
    for (int nt = 0; nt < 4; nt++) {
        int dc = wd * 32 + nt * 8 + tig * 2;
        int o00 = accL[nt][0] + (accH[nt][0] << 7);
        int o01 = accL[nt][1] + (accH[nt][1] << 7);
        int o10 = accL[nt][2] + (accH[nt][2] << 7);
        int o11 = accL[nt][3] + (accH[nt][3] << 7);
        sB[bl0][dc]     = (unsigned char)((o00 < 0 ? 1u : 0u) | (o00 != 0 ? 2u : 0u));
        sB[bl0][dc + 1] = (unsigned char)((o01 < 0 ? 1u : 0u) | (o01 != 0 ? 2u : 0u));
        sB[bl1][dc]     = (unsigned char)((o10 < 0 ? 1u : 0u) | (o10 != 0 ? 2u : 0u));
        sB[bl1][dc + 1] = (unsigned char)((o11 < 0 ? 1u : 0u) | (o11 != 0 ? 2u : 0u));
    }
    __syncthreads();

    int ldiff = 0;
    int t = threadIdx.x;
    if (t < 128) {
        int bl = t >> 1;
        int wsel = t & 1;
        unsigned ws = 0, wm = 0;
        #pragma unroll
        for (int n = 0; n < 32; n++) {
            unsigned byte = sB[bl][wsel * 32 + n];
            ws |= (byte & 1u) << n;
            wm |= ((byte >> 1) & 1u) << n;
        }
        size_t o = ((size_t)(b0 + bl) * FDIM + f) * WDIM + (d0 >> 5) + wsel;
        if (ws != g_eS[o] || wm != g_eM[o]) ldiff = 1;
        g_eS[o] = ws;
        g_eM[o] = wm;
    }
    if (ldiff) g_diff = 1;
}

// ---------------------------------------------------------------------------
__global__ void step_kernel() {
    if (g_done) return;
    g_k = g_k + 1;
    if (g_diff == 0) g_done = 1;
    g_diff = 0;
}

// ---------------------------------------------------------------------------
// argmax over m (first-index tie-break) + write k.  Output dtype: float32.
// ---------------------------------------------------------------------------
__global__ void argmax_kernel(float* __restrict__ out, int out_size) {
    int gtid = blockIdx.x * blockDim.x + threadIdx.x;
    int w = gtid >> 5;
    int lane = gtid & 31;
    if (w < BDIM * FDIM) {
        const float* srow = g_sim + (size_t)w * MDIM;
        float bv = -3.0e38f;
        int bi = 0;
        for (int m = lane; m < MDIM; m += 32) {
            float v = srow[m];
            if (v > bv) { bv = v; bi = m; }
        }
        for (int off = 16; off > 0; off >>= 1) {
            float ov = __shfl_down_sync(0xffffffffu, bv, off);
            int oi = __shfl_down_sync(0xffffffffu, bi, off);
            if (ov > bv || (ov == bv && oi < bi)) { bv = ov; bi = oi; }
        }
        if (lane == 0) out[w] = (float)bi;
    }
    if (gtid == 0 && out_size > BDIM * FDIM) out[BDIM * FDIM] = (float)g_k;
}

// ---------------------------------------------------------------------------
extern "C" void kernel_launch(void* const* d_in, const int* in_sizes, int n_in,
                              void* d_out, int out_size) {
    const float* inp;
    const float* cb;
    if (in_sizes[0] < in_sizes[1]) { inp = (const float*)d_in[0]; cb = (const float*)d_in[1]; }
    else                           { inp = (const float*)d_in[1]; cb = (const float*)d_in[0]; }
    float* out = (float*)d_out;

    colsum_kernel<<<dim3(8, FDIM), 256>>>(cb);
    pfactor_kernel<<<DDIM / 256, 256>>>();
    pack_cb_kernel<<<(FDIM * MDIM * DDIM) / 256, 256>>>(cb);
    pack_inp_kernel<<<(BDIM * DDIM) / 256, 256>>>(inp);
    cb_permute_kernel<<<dim3(DDIM / 32, FDIM), 256>>>(cb);

    // ---- stage 0 (float path; A = inp * P built on the fly) ----
    zero_sim_kernel<<<(BDIM * FDIM * MDIM) / 256, 256>>>();
    gemm1_f32_kernel<<<dim3(16, FDIM, 8), 256>>>(cb, inp);
    gemm2_f32_kernel<<<dim3(DDIM / 64, BDIM / 64, FDIM), 256>>>(cb);
    step_kernel<<<1, 1>>>();

    // ---- stages 1..9 (packed + IMMA path) ----
    for (int it = 1; it < NITERS; it++) {
        newest_bits_kernel<<<(BDIM * WDIM) / 256, 256>>>();
        gemm1_packed_kernel<<<dim3(BDIM / 32, MDIM / 32, FDIM), 256>>>(0, 1);
        gemm2_imma_kernel<<<dim3(DDIM / 64, BDIM / 64, FDIM), 256>>>();
        step_kernel<<<1, 1>>>();
    }

    // ---- final similarity from converged packed est, argmax + k ----
    gemm1_packed_kernel<<<dim3(BDIM / 32, MDIM / 32, FDIM), 256>>>(1, 0);
    argmax_kernel<<<(BDIM * FDIM * 32) / 256, 256>>>(out, out_size);
}

// round 11
// speedup vs baseline: 1.3705x; 1.0259x over previous
#include <cuda_runtime.h>
#include <cstdint>

#define BDIM 256
#define FDIM 4
#define MDIM 256
#define DDIM 8192
#define WDIM 256          // DDIM/32 packed words
#define NITERS 10

// Scratch (device globals -- allocation is forbidden)
__device__ float g_sim[BDIM * FDIM * MDIM];       // 1 MB
__device__ float g_colsum[FDIM * DDIM];           // stage-0 est (b-independent)
__device__ float g_P[FDIM * DDIM];                // prod of other 3 colsums
__device__ unsigned g_eS[BDIM * FDIM * WDIM];     // packed est sign bits (canonical S&M)
__device__ unsigned g_eM[BDIM * FDIM * WDIM];     // packed est nonzero mask
__device__ unsigned g_iS[BDIM * WDIM];            // packed inp sign bits
__device__ unsigned g_cbSt[FDIM * WDIM * MDIM];   // cb sign bits transposed [f][w][m]
// IMMA operands in warp-LDG-linear fragment order:
__device__ unsigned g_simLoP[(BDIM / 16) * FDIM * 1024]; // A tiles: 16 b-rows x 256 k
__device__ unsigned g_simHiP[(BDIM / 16) * FDIM * 1024];
__device__ unsigned g_cbP[(DDIM / 32) * FDIM * 2048];    // B tiles: 32 d-rows x 256 k
__device__ int g_done;
__device__ int g_diff;
__device__ int g_k;
__device__ unsigned g_ticket;

// ---------------------------------------------------------------------------
// colsum + P factors + zero sim + flags.  grid 32, block 256 (1 d per thread).
// Exact: colsums are integers |.|<=256; products <= 2^24 exact in fp32.
// ---------------------------------------------------------------------------
__global__ void colsum_pf_kernel(const float* __restrict__ cb) {
    int d = blockIdx.x * 256 + threadIdx.x;
    float s[4];
    #pragma unroll
    for (int f = 0; f < 4; f++) {
        const float* p = cb + ((size_t)f * MDIM) * DDIM + d;
        float acc = 0.f;
        for (int m = 0; m < MDIM; m++) acc += p[(size_t)m * DDIM];
        s[f] = acc;
        g_colsum[f * DDIM + d] = acc;
    }
    g_P[d]            = (s[1] * s[2]) * s[3];
    g_P[DDIM + d]     = (s[0] * s[2]) * s[3];
    g_P[2 * DDIM + d] = (s[0] * s[1]) * s[3];
    g_P[3 * DDIM + d] = (s[0] * s[1]) * s[2];
    int t = blockIdx.x * 256 + threadIdx.x;
    for (int i = t; i < BDIM * FDIM * MDIM; i += 32 * 256) g_sim[i] = 0.f;
    if (t == 0) { g_done = 0; g_diff = 0; g_k = 0; g_ticket = 0; }
}

// ---------------------------------------------------------------------------
// pack cb signs + inp signs + cb int8 fragment-permute, one branched kernel.
// grid = 32768 (cb signs) + 8192 (inp signs) + 1024 (permute) = 41984 blocks.
// ---------------------------------------------------------------------------
__global__ void pack_all_kernel(const float* __restrict__ cb,
                                const float* __restrict__ inp) {
    __shared__ signed char t[32][260];
    int bx = blockIdx.x;
    if (bx < 32768) {
        int idx = bx * 256 + threadIdx.x;      // (f*M+m)*8192 + d
        float v = cb[idx];
        unsigned neg = __ballot_sync(0xffffffffu, v < 0.f);
        if ((threadIdx.x & 31) == 0) {
            int fm = idx >> 13;
            int d = idx & (DDIM - 1);
            g_cbSt[((size_t)(fm >> 8) * WDIM + (d >> 5)) * MDIM + (fm & 255)] = neg;
        }
    } else if (bx < 40960) {
        int idx = (bx - 32768) * 256 + threadIdx.x;  // b*8192 + d
        unsigned neg = __ballot_sync(0xffffffffu, inp[idx] < 0.f);
        if ((threadIdx.x & 31) == 0) {
            int b = idx >> 13;
            int d = idx & (DDIM - 1);
            g_iS[(size_t)b * WDIM + (d >> 5)] = neg;
        }
    } else {
        int pb = bx - 40960;                   // 0..1023
        int d0 = (pb >> 2) * 32;
        int f = pb & 3;
        for (int idx = threadIdx.x; idx < 256 * 32; idx += 256) {
            int m = idx >> 5;
            int dl = idx & 31;
            t[dl][m] = (signed char)cb[((size_t)f * MDIM + m) * DDIM + d0 + dl];
        }
        __syncthreads();
        unsigned tile = (unsigned)((pb >> 2) * FDIM + f) * 2048;
        for (int widx = threadIdx.x; widx < 2048; widx += 256) {
            int dl = widx >> 6;
            int w = widx & 63;
            unsigned v = (unsigned)(unsigned char)t[dl][4 * w]
                       | ((unsigned)(unsigned char)t[dl][4 * w + 1] << 8)
                       | ((unsigned)(unsigned char)t[dl][4 * w + 2] << 16)
                       | ((unsigned)(unsigned char)t[dl][4 * w + 3] << 24);
            int nt = dl >> 3, g = dl & 7;
            int tig = w & 3, i = w >> 2, q = i >> 2, rem = i & 3;
            g_cbP[tile + (unsigned)(((nt * 4 + q) * 32 + g * 4 + tig) * 4 + rem)] = v;
        }
    }
}

// ---------------------------------------------------------------------------
// last-block step: diff-reduce across block, ticket, then k/done update.
// ---------------------------------------------------------------------------
__device__ __forceinline__ void last_block_step(int ldiff, int nblocks) {
    int any = __syncthreads_or(ldiff);
    if (threadIdx.x == 0) {
        if (any) atomicOr(&g_diff, 1);
        __threadfence();
        unsigned tk = atomicAdd(&g_ticket, 1u);
        if (tk == (unsigned)(nblocks - 1)) {
            g_ticket = 0;
            g_k = g_k + 1;
            if (atomicAdd(&g_diff, 0) == 0) g_done = 1;
            g_diff = 0;
        }
    }
}

// ---------------------------------------------------------------------------
// stage-0 GEMM1 (float, split-K=8 atomicAdd), A = inp * P on the fly
// ---------------------------------------------------------------------------
__global__ void gemm1_f32_kernel(const float* __restrict__ cb,
                                 const float* __restrict__ inp) {
    if (g_done) return;
    int bt = blockIdx.x >> 2;
    int mt = blockIdx.x & 3;
    int f = blockIdx.y;
    int b0 = bt * 64;
    int m0 = mt * 64;
    int k0 = blockIdx.z * (DDIM / 8);

    __shared__ float As[32][68];
    __shared__ float Bs[32][68];

    int tx = threadIdx.x & 15;
    int ty = threadIdx.x >> 4;

    float acc[4][4];
    for (int i = 0; i < 4; i++)
        for (int j = 0; j < 4; j++) acc[i][j] = 0.f;

    for (int kk = 0; kk < DDIM / 8; kk += 32) {
        for (int e = threadIdx.x; e < 2048; e += 256) {
            int r = e >> 5;
            int c = e & 31;
            int d = k0 + kk + c;
            As[c][r] = inp[(size_t)(b0 + r) * DDIM + d] * g_P[(size_t)f * DDIM + d];
            Bs[c][r] = cb[((size_t)f * MDIM + m0 + r) * DDIM + d];
        }
        __syncthreads();
        #pragma unroll
        for (int k = 0; k < 32; k++) {
            float a0 = As[k][tx * 4 + 0];
            float a1 = As[k][tx * 4 + 1];
            float a2 = As[k][tx * 4 + 2];
            float a3 = As[k][tx * 4 + 3];
            float c0 = Bs[k][ty * 4 + 0];
            float c1 = Bs[k][ty * 4 + 1];
            float c2 = Bs[k][ty * 4 + 2];
            float c3 = Bs[k][ty * 4 + 3];
            acc[0][0] += a0 * c0; acc[0][1] += a0 * c1; acc[0][2] += a0 * c2; acc[0][3] += a0 * c3;
            acc[1][0] += a1 * c0; acc[1][1] += a1 * c1; acc[1][2] += a1 * c2; acc[1][3] += a1 * c3;
            acc[2][0] += a2 * c0; acc[2][1] += a2 * c1; acc[2][2] += a2 * c2; acc[2][3] += a2 * c3;
            acc[3][0] += a3 * c0; acc[3][1] += a3 * c1; acc[3][2] += a3 * c2; acc[3][3] += a3 * c3;
        }
        __syncthreads();
    }
    for (int i = 0; i < 4; i++)
        for (int j = 0; j < 4; j++) {
            int b = b0 + tx * 4 + i;
            int m = m0 + ty * 4 + j;
            atomicAdd(&g_sim[((size_t)b * FDIM + f) * MDIM + m], acc[i][j]);
        }
}

// ---------------------------------------------------------------------------
// stage-0 GEMM2 (float) + sign + convergence (vs colsum) + PACKED est + step
// ---------------------------------------------------------------------------
__global__ void gemm2_f32_kernel(const float* __restrict__ cb) {
    if (g_done) return;
    int f = blockIdx.z;
    int b0 = blockIdx.y * 64;
    int d0 = blockIdx.x * 64;

    __shared__ float As[32][68];
    __shared__ float Bs[32][68];
    __shared__ unsigned char nibS[64][16];
    __shared__ unsigned char nibM[64][16];

    int tx = threadIdx.x & 15;      // d-group
    int ty = threadIdx.x >> 4;      // b-group

    float acc[4][4];
    for (int i = 0; i < 4; i++)
        for (int j = 0; j < 4; j++) acc[i][j] = 0.f;

    for (int mb = 0; mb < MDIM; mb += 32) {
        for (int e = threadIdx.x; e < 2048; e += 256) {
            int r = e >> 5;
            int c = e & 31;
            As[c][r] = g_sim[((size_t)(b0 + r) * FDIM + f) * MDIM + mb + c];
        }
        for (int e = threadIdx.x; e < 2048; e += 256) {
            int m = e >> 6;
            int dd = e & 63;
            Bs[m][dd] = cb[((size_t)f * MDIM + mb + m) * DDIM + d0 + dd];
        }
        __syncthreads();
        #pragma unroll
        for (int m = 0; m < 32; m++) {
            float a0 = As[m][ty * 4 + 0];
            float a1 = As[m][ty * 4 + 1];
            float a2 = As[m][ty * 4 + 2];
            float a3 = As[m][ty * 4 + 3];
            float c0 = Bs[m][tx * 4 + 0];
            float c1 = Bs[m][tx * 4 + 1];
            float c2 = Bs[m][tx * 4 + 2];
            float c3 = Bs[m][tx * 4 + 3];
            acc[0][0] += a0 * c0; acc[0][1] += a0 * c1; acc[0][2] += a0 * c2; acc[0][3] += a0 * c3;
            acc[1][0] += a1 * c0; acc[1][1] += a1 * c1; acc[1][2] += a1 * c2; acc[1][3] += a1 * c3;
            acc[2][0] += a2 * c0; acc[2][1] += a2 * c1; acc[2][2] += a2 * c2; acc[2][3] += a2 * c3;
            acc[3][0] += a3 * c0; acc[3][1] += a3 * c1; acc[3][2] += a3 * c2; acc[3][3] += a3 * c3;
        }
        __syncthreads();
    }

    int ldiff = 0;
    #pragma unroll
    for (int i = 0; i < 4; i++) {
        unsigned sn = 0, mn = 0;
        #pragma unroll
        for (int j = 0; j < 4; j++) {
            float v = acc[i][j];
            float s = (v > 0.f) ? 1.f : ((v < 0.f) ? -1.f : 0.f);
            int d = d0 + tx * 4 + j;
            if (s != g_colsum[(size_t)f * DDIM + d]) ldiff = 1;
            if (v < 0.f) sn |= (1u << j);
            if (v != 0.f) mn |= (1u << j);
        }
        nibS[ty * 4 + i][tx] = (unsigned char)sn;
        nibM[ty * 4 + i][tx] = (unsigned char)mn;
    }
    __syncthreads();

    int t = threadIdx.x;
    if (t < 128) {
        int bl = t >> 1;
        int wsel = t & 1;
        unsigned ws = 0, wm = 0;
        #pragma unroll
        for (int n = 0; n < 8; n++) {
            ws |= (unsigned)nibS[bl][wsel * 8 + n] << (4 * n);
            wm |= (unsigned)nibM[bl][wsel * 8 + n] << (4 * n);
        }
        size_t o = ((size_t)(b0 + bl) * FDIM + f) * WDIM + (d0 >> 5) + wsel;
        g_eS[o] = ws;
        g_eM[o] = wm;
    }
    last_block_step(ldiff, 2048);
}

// ---------------------------------------------------------------------------
// packed GEMM1 with FUSED newest (src_est=0) or est source (src_est=1).
// sim = nz - 2*popc((Sa^Sb)&Ma).
// src_est=0: writes int8 planes only.  src_est=1: writes f32 sim only.
// ---------------------------------------------------------------------------
__global__ void gemm1_packed_kernel(int src_est, int respect_done) {
    if (respect_done && g_done) return;
    int b0 = blockIdx.x * 32;
    int m0 = blockIdx.y * 32;
    int f = blockIdx.z;
    int f1 = (f + 1) & 3, f2 = (f + 2) & 3, f3 = (f + 3) & 3;

    __shared__ unsigned AS[32][33];
    __shared__ unsigned AM[32][33];
    __shared__ unsigned BS[32][33];

    int tx = threadIdx.x & 15;
    int ty = threadIdx.x >> 4;

    int acc[2][2] = {{0, 0}, {0, 0}};
    int accM[2] = {0, 0};

    for (int w0 = 0; w0 < WDIM; w0 += 32) {
        if (src_est) {
            for (int e = threadIdx.x; e < 1024; e += 256) {
                int r = e >> 5;
                int c = e & 31;
                size_t src = ((size_t)(b0 + r) * FDIM + f) * WDIM + w0 + c;
                AS[c][r] = g_eS[src];
                AM[c][r] = g_eM[src];
            }
        } else {
            // inline newest: S_f = (iS ^ s_o1 ^ s_o2 ^ s_o3) & (m_o1 & m_o2 & m_o3)
            for (int e = threadIdx.x; e < 1024; e += 256) {
                int r = e >> 5;
                int c = e & 31;
                int b = b0 + r;
                int w = w0 + c;
                size_t base = ((size_t)b * FDIM) * WDIM + w;
                unsigned so1 = g_eS[base + (size_t)f1 * WDIM];
                unsigned so2 = g_eS[base + (size_t)f2 * WDIM];
                unsigned so3 = g_eS[base + (size_t)f3 * WDIM];
                unsigned mo1 = g_eM[base + (size_t)f1 * WDIM];
                unsigned mo2 = g_eM[base + (size_t)f2 * WDIM];
                unsigned mo3 = g_eM[base + (size_t)f3 * WDIM];
                unsigned Mf = mo1 & mo2 & mo3;
                unsigned Sf = (g_iS[(size_t)b * WDIM + w] ^ so1 ^ so2 ^ so3) & Mf;
                AS[c][r] = Sf;
                AM[c][r] = Mf;
            }
        }
        for (int e = threadIdx.x; e < 1024; e += 256) {
            int w = e >> 5;
            int m = e & 31;
            BS[w][m] = g_cbSt[((size_t)f * WDIM + w0 + w) * MDIM + m0 + m];
        }
        __syncthreads();
        #pragma unroll
        for (int w = 0; w < 32; w++) {
            unsigned sa0 = AS[w][tx * 2 + 0];
            unsigned sa1 = AS[w][tx * 2 + 1];
            unsigned ma0 = AM[w][tx * 2 + 0];
            unsigned ma1 = AM[w][tx * 2 + 1];
            unsigned sb0 = BS[w][ty * 2 + 0];
            unsigned sb1 = BS[w][ty * 2 + 1];
            accM[0] += __popc(ma0);
            accM[1] += __popc(ma1);
            acc[0][0] += __popc((sa0 ^ sb0) & ma0);
            acc[0][1] += __popc((sa0 ^ sb1) & ma0);
            acc[1][0] += __popc((sa1 ^ sb0) & ma1);
            acc[1][1] += __popc((sa1 ^ sb1) & ma1);
        }
        __syncthreads();
    }

    unsigned char* loB = (unsigned char*)g_simLoP;
    unsigned char* hiB = (unsigned char*)g_simHiP;
    #pragma unroll
    for (int i = 0; i < 2; i++) {
        int b = b0 + tx * 2 + i;
        int tileA = ((b >> 4) * FDIM + f) * 4096;
        int bl = b & 15;
        int gg = bl & 7;
        int half = bl >> 3;
        #pragma unroll
        for (int j = 0; j < 2; j++) {
            int m = m0 + ty * 2 + j;
            int sim = accM[i] - 2 * acc[i][j];
            if (src_est) {
                g_sim[((size_t)b * FDIM + f) * MDIM + m] = (float)sim;
            } else {
                int hi = (sim + 64) >> 7;
                int lo = sim - (hi << 7);
                int w = m >> 2, tig = w & 3, ii = w >> 2, q = ii >> 2, rem = ii & 3;
                int bidx = tileA + (((half * 4 + q) * 32 + gg * 4 + tig) * 4 + rem) * 4 + (m & 3);
                loB[bidx] = (unsigned char)(signed char)lo;
                hiB[bidx] = (unsigned char)(signed char)hi;
            }
        }
    }
}

// ---------------------------------------------------------------------------
// packed GEMM2 via IMMA (fragment-order operands, all LDG.128) + step.
// ---------------------------------------------------------------------------
__device__ __forceinline__ void imma16832(int& c0, int& c1, int& c2, int& c3,
                                          unsigned a0, unsigned a1, unsigned a2, unsigned a3,
                                          unsigned b0, unsigned b1) {
    asm volatile(
        "mma.sync.aligned.m16n8k32.row.col.s32.s8.s8.s32 "
        "{%0,%1,%2,%3}, {%4,%5,%6,%7}, {%8,%9}, {%0,%1,%2,%3};\n"
        : "+r"(c0), "+r"(c1), "+r"(c2), "+r"(c3)
        : "r"(a0), "r"(a1), "r"(a2), "r"(a3), "r"(b0), "r"(b1));
}

__global__ void gemm2_imma_kernel() {
    if (g_done) return;
    int f = blockIdx.z;
    int d0 = blockIdx.x * 64;
    int b0 = blockIdx.y * 64;
    int w = threadIdx.x >> 5;
    int lane = threadIdx.x & 31;
    int g = lane >> 2;
    int tig = lane & 3;
    int wb = w & 3;          // 4 b-warps
    int wd = w >> 2;         // 2 d-warps

    const uint4* Alo = (const uint4*)g_simLoP;
    const uint4* Ahi = (const uint4*)g_simHiP;
    const uint4* Bp  = (const uint4*)g_cbP;
    unsigned tA = (unsigned)(((b0 >> 4) + wb) * FDIM + f) * 256;   // uint4 units
    unsigned tB = (unsigned)(((d0 >> 5) + wd) * FDIM + f) * 512;   // uint4 units

    int accL[4][4];
    int accH[4][4];
    #pragma unroll
    for (int nt = 0; nt < 4; nt++)
        #pragma unroll
        for (int i = 0; i < 4; i++) { accL[nt][i] = 0; accH[nt][i] = 0; }

    #pragma unroll
    for (int q = 0; q < 4; q++) {
        uint4 al0 = Alo[tA + q * 32 + lane];
        uint4 al1 = Alo[tA + (4 + q) * 32 + lane];
        uint4 ah0 = Ahi[tA + q * 32 + lane];
        uint4 ah1 = Ahi[tA + (4 + q) * 32 + lane];
        uint4 bq0 = Bp[tB + (0 * 4 + q) * 32 + lane];
        uint4 bq1 = Bp[tB + (1 * 4 + q) * 32 + lane];
        uint4 bq2 = Bp[tB + (2 * 4 + q) * 32 + lane];
        uint4 bq3 = Bp[tB + (3 * 4 + q) * 32 + lane];
        imma16832(accL[0][0], accL[0][1], accL[0][2], accL[0][3], al0.x, al1.x, al0.y, al1.y, bq0.x, bq0.y);
        imma16832(accL[1][0], accL[1][1], accL[1][2], accL[1][3], al0.x, al1.x, al0.y, al1.y, bq1.x, bq1.y);
        imma16832(accL[2][0], accL[2][1], accL[2][2], accL[2][3], al0.x, al1.x, al0.y, al1.y, bq2.x, bq2.y);
        imma16832(accL[3][0], accL[3][1], accL[3][2], accL[3][3], al0.x, al1.x, al0.y, al1.y, bq3.x, bq3.y);
        imma16832(accH[0][0], accH[0][1], accH[0][2], accH[0][3], ah0.x, ah1.x, ah0.y, ah1.y, bq0.x, bq0.y);
        imma16832(accH[1][0], accH[1][1], accH[1][2], accH[1][3], ah0.x, ah1.x, ah0.y, ah1.y, bq1.x, bq1.y);
        imma16832(accH[2][0], accH[2][1], accH[2][2], accH[2][3], ah0.x, ah1.x, ah0.y, ah1.y, bq2.x, bq2.y);
        imma16832(accH[3][0], accH[3][1], accH[3][2], accH[3][3], ah0.x, ah1.x, ah0.y, ah1.y, bq3.x, bq3.y);
        imma16832(accL[0][0], accL[0][1], accL[0][2], accL[0][3], al0.z, al1.z, al0.w, al1.w, bq0.z, bq0.w);
        imma16832(accL[1][0], accL[1][1], accL[1][2], accL[1][3], al0.z, al1.z, al0.w, al1.w, bq1.z, bq1.w);
        imma16832(accL[2][0], accL[2][1], accL[2][2], accL[2][3], al0.z, al1.z, al0.w, al1.w, bq2.z, bq2.w);
        imma16832(accL[3][0], accL[3][1], accL[3][2], accL[3][3], al0.z, al1.z, al0.w, al1.w, bq3.z, bq3.w);
        imma16832(accH[0][0], accH[0][1], accH[0][2], accH[0][3], ah0.z, ah1.z, ah0.w, ah1.w, bq0.z, bq0.w);
        imma16832(accH[1][0], accH[1][1], accH[1][2], accH[1][3], ah0.z, ah1.z, ah0.w, ah1.w, bq1.z, bq1.w);
        imma16832(accH[2][0], accH[2][1], accH[2][2], accH[2][3], ah0.z, ah1.z, ah0.w, ah1.w, bq2.z, bq2.w);
        imma16832(accH[3][0], accH[3][1], accH[3][2], accH[3][3], ah0.z, ah1.z, ah0.w, ah1.w, bq3.z, bq3.w);
    }

    __shared__ unsigned char sB[64][64];   // bit0 = sign, bit1 = nonzero
    int bl0 = wb * 16 + g;
    int bl1 = bl0 + 8;
    #pragma unroll
    for (int nt = 0; nt < 4; nt++) {
        int dc = wd * 32 + nt * 8 + tig * 2;
        int o00 = accL[nt][0] + (accH[nt][0] << 7);
        int o01 = accL[nt][1] + (accH[nt][1] << 7);
        int o10 = accL[nt][2] + (accH[nt][2] << 7);
        int o11 = accL[nt][3] + (accH[nt][3] << 7);
        sB[bl0][dc]     = (unsigned char)((o00 < 0 ? 1u : 0u) | (o00 != 0 ? 2u : 0u));
        sB[bl0][dc + 1] = (unsigned char)((o01 < 0 ? 1u : 0u) | (o01 != 0 ? 2u : 0u));
        sB[bl1][dc]     = (unsigned char)((o10 < 0 ? 1u : 0u) | (o10 != 0 ? 2u : 0u));
        sB[bl1][dc + 1] = (unsigned char)((o11 < 0 ? 1u : 0u) | (o11 != 0 ? 2u : 0u));
    }
    __syncthreads();

    int ldiff = 0;
    int t = threadIdx.x;
    if (t < 128) {
        int bl = t >> 1;
        int wsel = t & 1;
        unsigned ws = 0, wm = 0;
        #pragma unroll
        for (int n = 0; n < 32; n++) {
            unsigned byte = sB[bl][wsel * 32 + n];
            ws |= (byte & 1u) << n;
            wm |= ((byte >> 1) & 1u) << n;
        }
        size_t o = ((size_t)(b0 + bl) * FDIM + f) * WDIM + (d0 >> 5) + wsel;
        if (ws != g_eS[o] || wm != g_eM[o]) ldiff = 1;
        g_eS[o] = ws;
        g_eM[o] = wm;
    }
    last_block_step(ldiff, 2048);
}

// ---------------------------------------------------------------------------
// argmax over m (first-index tie-break) + write k.  Output dtype: float32.
// ---------------------------------------------------------------------------
__global__ void argmax_kernel(float* __restrict__ out, int out_size) {
    int gtid = blockIdx.x * blockDim.x + threadIdx.x;
    int w = gtid >> 5;
    int lane = gtid & 31;
    if (w < BDIM * FDIM) {
        const float* srow = g_sim + (size_t)w * MDIM;
        float bv = -3.0e38f;
        int bi = 0;
        for (int m = lane; m < MDIM; m += 32) {
            float v = srow[m];
            if (v > bv) { bv = v; bi = m; }
        }
        for (int off = 16; off > 0; off >>= 1) {
            float ov = __shfl_down_sync(0xffffffffu, bv, off);
            int oi = __shfl_down_sync(0xffffffffu, bi, off);
            if (ov > bv || (ov == bv && oi < bi)) { bv = ov; bi = oi; }
        }
        if (lane == 0) out[w] = (float)bi;
    }
    if (gtid == 0 && out_size > BDIM * FDIM) out[BDIM * FDIM] = (float)g_k;
}

// ---------------------------------------------------------------------------
extern "C" void kernel_launch(void* const* d_in, const int* in_sizes, int n_in,
                              void* d_out, int out_size) {
    const float* inp;
    const float* cb;
    if (in_sizes[0] < in_sizes[1]) { inp = (const float*)d_in[0]; cb = (const float*)d_in[1]; }
    else                           { inp = (const float*)d_in[1]; cb = (const float*)d_in[0]; }
    float* out = (float*)d_out;

    // launch #0..#5: colsum_pf, pack_all, g1f32, g2f32, g1packed, g2imma (ncu target)
    colsum_pf_kernel<<<32, 256>>>(cb);
    pack_all_kernel<<<41984, 256>>>(cb, inp);
    gemm1_f32_kernel<<<dim3(16, FDIM, 8), 256>>>(cb, inp);
    gemm2_f32_kernel<<<dim3(DDIM / 64, BDIM / 64, FDIM), 256>>>(cb);

    for (int it = 1; it < NITERS; it++) {
        gemm1_packed_kernel<<<dim3(BDIM / 32, MDIM / 32, FDIM), 256>>>(0, 1);
        gemm2_imma_kernel<<<dim3(DDIM / 64, BDIM / 64, FDIM), 256>>>();
    }

    gemm1_packed_kernel<<<dim3(BDIM / 32, MDIM / 32, FDIM), 256>>>(1, 0);
    argmax_kernel<<<(BDIM * FDIM * 32) / 256, 256>>>(out, out_size);
}

// round 12
// speedup vs baseline: 1.3854x; 1.0108x over previous
#include <cuda_runtime.h>
#include <cstdint>

#define BDIM 256
#define FDIM 4
#define MDIM 256
#define DDIM 8192
#define WDIM 256          // DDIM/32 packed words
#define NITERS 10

// Scratch (device globals -- allocation is forbidden)
__device__ float g_sim[BDIM * FDIM * MDIM];       // 1 MB
__device__ float g_colsum[FDIM * DDIM];           // stage-0 est (b-independent)
__device__ float g_P[FDIM * DDIM];                // prod of other 3 colsums
__device__ unsigned g_eS[BDIM * FDIM * WDIM];     // packed est sign bits (canonical S&M)
__device__ unsigned g_eM[BDIM * FDIM * WDIM];     // packed est nonzero mask
__device__ unsigned g_iS[BDIM * WDIM];            // packed inp sign bits
__device__ unsigned g_cbSt[FDIM * WDIM * MDIM];   // cb sign bits transposed [f][w][m]
// IMMA operands in warp-LDG-linear fragment order:
__device__ unsigned g_simLoP[(BDIM / 16) * FDIM * 1024]; // A tiles: 16 b-rows x 256 k
__device__ unsigned g_simHiP[(BDIM / 16) * FDIM * 1024];
__device__ unsigned g_cbP[(DDIM / 32) * FDIM * 2048];    // B tiles: 32 d-rows x 256 k
__device__ int g_done;
__device__ int g_diff;
__device__ int g_k;
__device__ unsigned g_ticket;

// ---------------------------------------------------------------------------
// colsum + P factors + zero sim + flags.  grid 32, block 256.
// ---------------------------------------------------------------------------
__global__ void colsum_pf_kernel(const float* __restrict__ cb) {
    int d = blockIdx.x * 256 + threadIdx.x;
    float s[4];
    #pragma unroll
    for (int f = 0; f < 4; f++) {
        const float* p = cb + ((size_t)f * MDIM) * DDIM + d;
        float acc = 0.f;
        for (int m = 0; m < MDIM; m++) acc += p[(size_t)m * DDIM];
        s[f] = acc;
        g_colsum[f * DDIM + d] = acc;
    }
    g_P[d]            = (s[1] * s[2]) * s[3];
    g_P[DDIM + d]     = (s[0] * s[2]) * s[3];
    g_P[2 * DDIM + d] = (s[0] * s[1]) * s[3];
    g_P[3 * DDIM + d] = (s[0] * s[1]) * s[2];
    int t = blockIdx.x * 256 + threadIdx.x;
    for (int i = t; i < BDIM * FDIM * MDIM; i += 32 * 256) g_sim[i] = 0.f;
    if (t == 0) { g_done = 0; g_diff = 0; g_k = 0; g_ticket = 0; }
}

// ---------------------------------------------------------------------------
// pack cb signs + inp signs + cb int8 fragment-permute, one branched kernel.
// ---------------------------------------------------------------------------
__global__ void pack_all_kernel(const float* __restrict__ cb,
                                const float* __restrict__ inp) {
    __shared__ signed char t[32][260];
    int bx = blockIdx.x;
    if (bx < 32768) {
        int idx = bx * 256 + threadIdx.x;      // (f*M+m)*8192 + d
        float v = cb[idx];
        unsigned neg = __ballot_sync(0xffffffffu, v < 0.f);
        if ((threadIdx.x & 31) == 0) {
            int fm = idx >> 13;
            int d = idx & (DDIM - 1);
            g_cbSt[((size_t)(fm >> 8) * WDIM + (d >> 5)) * MDIM + (fm & 255)] = neg;
        }
    } else if (bx < 40960) {
        int idx = (bx - 32768) * 256 + threadIdx.x;  // b*8192 + d
        unsigned neg = __ballot_sync(0xffffffffu, inp[idx] < 0.f);
        if ((threadIdx.x & 31) == 0) {
            int b = idx >> 13;
            int d = idx & (DDIM - 1);
            g_iS[(size_t)b * WDIM + (d >> 5)] = neg;
        }
    } else {
        int pb = bx - 40960;                   // 0..1023
        int d0 = (pb >> 2) * 32;
        int f = pb & 3;
        for (int idx = threadIdx.x; idx < 256 * 32; idx += 256) {
            int m = idx >> 5;
            int dl = idx & 31;
            t[dl][m] = (signed char)cb[((size_t)f * MDIM + m) * DDIM + d0 + dl];
        }
        __syncthreads();
        unsigned tile = (unsigned)((pb >> 2) * FDIM + f) * 2048;
        for (int widx = threadIdx.x; widx < 2048; widx += 256) {
            int dl = widx >> 6;
            int w = widx & 63;
            unsigned v = (unsigned)(unsigned char)t[dl][4 * w]
                       | ((unsigned)(unsigned char)t[dl][4 * w + 1] << 8)
                       | ((unsigned)(unsigned char)t[dl][4 * w + 2] << 16)
                       | ((unsigned)(unsigned char)t[dl][4 * w + 3] << 24);
            int nt = dl >> 3, g = dl & 7;
            int tig = w & 3, i = w >> 2, q = i >> 2, rem = i & 3;
            g_cbP[tile + (unsigned)(((nt * 4 + q) * 32 + g * 4 + tig) * 4 + rem)] = v;
        }
    }
}

// ---------------------------------------------------------------------------
// last-block step: diff-reduce across block, ticket, then k/done update.
// ---------------------------------------------------------------------------
__device__ __forceinline__ void last_block_step(int ldiff, int nblocks) {
    int any = __syncthreads_or(ldiff);
    if (threadIdx.x == 0) {
        if (any) atomicOr(&g_diff, 1);
        __threadfence();
        unsigned tk = atomicAdd(&g_ticket, 1u);
        if (tk == (unsigned)(nblocks - 1)) {
            g_ticket = 0;
            g_k = g_k + 1;
            if (atomicAdd(&g_diff, 0) == 0) g_done = 1;
            g_diff = 0;
        }
    }
}

// ---------------------------------------------------------------------------
// stage-0 GEMM1 (float, split-K=8 atomicAdd), A = inp * P on the fly.
// float4 smem reads (2 LDS.128 + 16 FFMA per k).
// ---------------------------------------------------------------------------
__global__ void gemm1_f32_kernel(const float* __restrict__ cb,
                                 const float* __restrict__ inp) {
    if (g_done) return;
    int bt = blockIdx.x >> 2;
    int mt = blockIdx.x & 3;
    int f = blockIdx.y;
    int b0 = bt * 64;
    int m0 = mt * 64;
    int k0 = blockIdx.z * (DDIM / 8);

    __shared__ __align__(16) float As[32][68];
    __shared__ __align__(16) float Bs[32][68];

    int tx = threadIdx.x & 15;
    int ty = threadIdx.x >> 4;

    float acc[4][4];
    for (int i = 0; i < 4; i++)
        for (int j = 0; j < 4; j++) acc[i][j] = 0.f;

    for (int kk = 0; kk < DDIM / 8; kk += 32) {
        for (int e = threadIdx.x; e < 2048; e += 256) {
            int r = e >> 5;
            int c = e & 31;
            int d = k0 + kk + c;
            As[c][r] = inp[(size_t)(b0 + r) * DDIM + d] * g_P[(size_t)f * DDIM + d];
            Bs[c][r] = cb[((size_t)f * MDIM + m0 + r) * DDIM + d];
        }
        __syncthreads();
        #pragma unroll
        for (int k = 0; k < 32; k++) {
            float4 av = *(const float4*)&As[k][tx * 4];
            float4 bv = *(const float4*)&Bs[k][ty * 4];
            acc[0][0] += av.x * bv.x; acc[0][1] += av.x * bv.y; acc[0][2] += av.x * bv.z; acc[0][3] += av.x * bv.w;
            acc[1][0] += av.y * bv.x; acc[1][1] += av.y * bv.y; acc[1][2] += av.y * bv.z; acc[1][3] += av.y * bv.w;
            acc[2][0] += av.z * bv.x; acc[2][1] += av.z * bv.y; acc[2][2] += av.z * bv.z; acc[2][3] += av.z * bv.w;
            acc[3][0] += av.w * bv.x; acc[3][1] += av.w * bv.y; acc[3][2] += av.w * bv.z; acc[3][3] += av.w * bv.w;
        }
        __syncthreads();
    }
    for (int i = 0; i < 4; i++)
        for (int j = 0; j < 4; j++) {
            int b = b0 + tx * 4 + i;
            int m = m0 + ty * 4 + j;
            atomicAdd(&g_sim[((size_t)b * FDIM + f) * MDIM + m], acc[i][j]);
        }
}

// ---------------------------------------------------------------------------
// stage-0 GEMM2 (float) + sign + convergence (vs colsum) + PACKED est + step.
// float4 smem reads.
// ---------------------------------------------------------------------------
__global__ void gemm2_f32_kernel(const float* __restrict__ cb) {
    if (g_done) return;
    int f = blockIdx.z;
    int b0 = blockIdx.y * 64;
    int d0 = blockIdx.x * 64;

    __shared__ __align__(16) float As[32][68];
    __shared__ __align__(16) float Bs[32][68];
    __shared__ unsigned char nibS[64][16];
    __shared__ unsigned char nibM[64][16];

    int tx = threadIdx.x & 15;      // d-group
    int ty = threadIdx.x >> 4;      // b-group

    float acc[4][4];
    for (int i = 0; i < 4; i++)
        for (int j = 0; j < 4; j++) acc[i][j] = 0.f;

    for (int mb = 0; mb < MDIM; mb += 32) {
        for (int e = threadIdx.x; e < 2048; e += 256) {
            int r = e >> 5;
            int c = e & 31;
            As[c][r] = g_sim[((size_t)(b0 + r) * FDIM + f) * MDIM + mb + c];
        }
        for (int e = threadIdx.x; e < 2048; e += 256) {
            int m = e >> 6;
            int dd = e & 63;
            Bs[m][dd] = cb[((size_t)f * MDIM + mb + m) * DDIM + d0 + dd];
        }
        __syncthreads();
        #pragma unroll
        for (int m = 0; m < 32; m++) {
            float4 av = *(const float4*)&As[m][ty * 4];
            float4 bv = *(const float4*)&Bs[m][tx * 4];
            acc[0][0] += av.x * bv.x; acc[0][1] += av.x * bv.y; acc[0][2] += av.x * bv.z; acc[0][3] += av.x * bv.w;
            acc[1][0] += av.y * bv.x; acc[1][1] += av.y * bv.y; acc[1][2] += av.y * bv.z; acc[1][3] += av.y * bv.w;
            acc[2][0] += av.z * bv.x; acc[2][1] += av.z * bv.y; acc[2][2] += av.z * bv.z; acc[2][3] += av.z * bv.w;
            acc[3][0] += av.w * bv.x; acc[3][1] += av.w * bv.y; acc[3][2] += av.w * bv.z; acc[3][3] += av.w * bv.w;
        }
        __syncthreads();
    }

    int ldiff = 0;
    #pragma unroll
    for (int i = 0; i < 4; i++) {
        unsigned sn = 0, mn = 0;
        #pragma unroll
        for (int j = 0; j < 4; j++) {
            float v = acc[i][j];
            float s = (v > 0.f) ? 1.f : ((v < 0.f) ? -1.f : 0.f);
            int d = d0 + tx * 4 + j;
            if (s != g_colsum[(size_t)f * DDIM + d]) ldiff = 1;
            if (v < 0.f) sn |= (1u << j);
            if (v != 0.f) mn |= (1u << j);
        }
        nibS[ty * 4 + i][tx] = (unsigned char)sn;
        nibM[ty * 4 + i][tx] = (unsigned char)mn;
    }
    __syncthreads();

    int t = threadIdx.x;
    if (t < 128) {
        int bl = t >> 1;
        int wsel = t & 1;
        unsigned ws = 0, wm = 0;
        #pragma unroll
        for (int n = 0; n < 8; n++) {
            ws |= (unsigned)nibS[bl][wsel * 8 + n] << (4 * n);
            wm |= (unsigned)nibM[bl][wsel * 8 + n] << (4 * n);
        }
        size_t o = ((size_t)(b0 + bl) * FDIM + f) * WDIM + (d0 >> 5) + wsel;
        g_eS[o] = ws;
        g_eM[o] = wm;
    }
    last_block_step(ldiff, 2048);
}

// ---------------------------------------------------------------------------
// packed GEMM1 with FUSED newest (src_est=0) or est source (src_est=1).
// ---------------------------------------------------------------------------
__global__ void gemm1_packed_kernel(int src_est, int respect_done) {
    if (respect_done && g_done) return;
    int b0 = blockIdx.x * 32;
    int m0 = blockIdx.y * 32;
    int f = blockIdx.z;
    int f1 = (f + 1) & 3, f2 = (f + 2) & 3, f3 = (f + 3) & 3;

    __shared__ unsigned AS[32][33];
    __shared__ unsigned AM[32][33];
    __shared__ unsigned BS[32][33];

    int tx = threadIdx.x & 15;
    int ty = threadIdx.x >> 4;

    int acc[2][2] = {{0, 0}, {0, 0}};
    int accM[2] = {0, 0};

    for (int w0 = 0; w0 < WDIM; w0 += 32) {
        if (src_est) {
            for (int e = threadIdx.x; e < 1024; e += 256) {
                int r = e >> 5;
                int c = e & 31;
                size_t src = ((size_t)(b0 + r) * FDIM + f) * WDIM + w0 + c;
                AS[c][r] = g_eS[src];
                AM[c][r] = g_eM[src];
            }
        } else {
            for (int e = threadIdx.x; e < 1024; e += 256) {
                int r = e >> 5;
                int c = e & 31;
                int b = b0 + r;
                int w = w0 + c;
                size_t base = ((size_t)b * FDIM) * WDIM + w;
                unsigned so1 = g_eS[base + (size_t)f1 * WDIM];
                unsigned so2 = g_eS[base + (size_t)f2 * WDIM];
                unsigned so3 = g_eS[base + (size_t)f3 * WDIM];
                unsigned mo1 = g_eM[base + (size_t)f1 * WDIM];
                unsigned mo2 = g_eM[base + (size_t)f2 * WDIM];
                unsigned mo3 = g_eM[base + (size_t)f3 * WDIM];
                unsigned Mf = mo1 & mo2 & mo3;
                unsigned Sf = (g_iS[(size_t)b * WDIM + w] ^ so1 ^ so2 ^ so3) & Mf;
                AS[c][r] = Sf;
                AM[c][r] = Mf;
            }
        }
        for (int e = threadIdx.x; e < 1024; e += 256) {
            int w = e >> 5;
            int m = e & 31;
            BS[w][m] = g_cbSt[((size_t)f * WDIM + w0 + w) * MDIM + m0 + m];
        }
        __syncthreads();
        #pragma unroll
        for (int w = 0; w < 32; w++) {
            unsigned sa0 = AS[w][tx * 2 + 0];
            unsigned sa1 = AS[w][tx * 2 + 1];
            unsigned ma0 = AM[w][tx * 2 + 0];
            unsigned ma1 = AM[w][tx * 2 + 1];
            unsigned sb0 = BS[w][ty * 2 + 0];
            unsigned sb1 = BS[w][ty * 2 + 1];
            accM[0] += __popc(ma0);
            accM[1] += __popc(ma1);
            acc[0][0] += __popc((sa0 ^ sb0) & ma0);
            acc[0][1] += __popc((sa0 ^ sb1) & ma0);
            acc[1][0] += __popc((sa1 ^ sb0) & ma1);
            acc[1][1] += __popc((sa1 ^ sb1) & ma1);
        }
        __syncthreads();
    }

    unsigned char* loB = (unsigned char*)g_simLoP;
    unsigned char* hiB = (unsigned char*)g_simHiP;
    #pragma unroll
    for (int i = 0; i < 2; i++) {
        int b = b0 + tx * 2 + i;
        int tileA = ((b >> 4) * FDIM + f) * 4096;
        int bl = b & 15;
        int gg = bl & 7;
        int half = bl >> 3;
        #pragma unroll
        for (int j = 0; j < 2; j++) {
            int m = m0 + ty * 2 + j;
            int sim = accM[i] - 2 * acc[i][j];
            if (src_est) {
                g_sim[((size_t)b * FDIM + f) * MDIM + m] = (float)sim;
            } else {
                int hi = (sim + 64) >> 7;
                int lo = sim - (hi << 7);
                int w = m >> 2, tig = w & 3, ii = w >> 2, q = ii >> 2, rem = ii & 3;
                int bidx = tileA + (((half * 4 + q) * 32 + gg * 4 + tig) * 4 + rem) * 4 + (m & 3);
                loB[bidx] = (unsigned char)(signed char)lo;
                hiB[bidx] = (unsigned char)(signed char)hi;
            }
        }
    }
}

// ---------------------------------------------------------------------------
// packed GEMM2 via IMMA, smem-staged operands (48KB static) + step.
// ---------------------------------------------------------------------------
__device__ __forceinline__ void imma16832(int& c0, int& c1, int& c2, int& c3,
                                          unsigned a0, unsigned a1, unsigned a2, unsigned a3,
                                          unsigned b0, unsigned b1) {
    asm volatile(
        "mma.sync.aligned.m16n8k32.row.col.s32.s8.s8.s32 "
        "{%0,%1,%2,%3}, {%4,%5,%6,%7}, {%8,%9}, {%0,%1,%2,%3};\n"
        : "+r"(c0), "+r"(c1), "+r"(c2), "+r"(c3)
        : "r"(a0), "r"(a1), "r"(a2), "r"(a3), "r"(b0), "r"(b1));
}

__global__ void gemm2_imma_kernel() {
    if (g_done) return;
    __shared__ __align__(16) unsigned char smem_raw[49152];
    uint4* sALo = (uint4*)smem_raw;                  // 1024 uint4: 4 wb-tiles x 256
    uint4* sAHi = (uint4*)(smem_raw + 16384);        // 1024 uint4
    uint4* sBt  = (uint4*)(smem_raw + 32768);        // 1024 uint4: 2 wd-tiles x 512
    unsigned char (*sB)[64] = (unsigned char(*)[64])smem_raw;  // epilogue reuse

    int f = blockIdx.z;
    int d0 = blockIdx.x * 64;
    int b0 = blockIdx.y * 64;
    int w = threadIdx.x >> 5;
    int lane = threadIdx.x & 31;
    int g = lane >> 2;
    int tig = lane & 3;
    int wb = w & 3;          // 4 b-warps
    int wd = w >> 2;         // 2 d-warps

    // stage tiles (coalesced LDG.128)
    {
        const uint4* Alo = (const uint4*)g_simLoP;
        const uint4* Ahi = (const uint4*)g_simHiP;
        const uint4* Bp  = (const uint4*)g_cbP;
        for (int i = threadIdx.x; i < 1024; i += 256) {
            int tw = i >> 8;                 // wb tile
            int off = i & 255;
            unsigned src = (unsigned)(((b0 >> 4) + tw) * FDIM + f) * 256 + off;
            sALo[i] = Alo[src];
            sAHi[i] = Ahi[src];
        }
        for (int i = threadIdx.x; i < 1024; i += 256) {
            int tw = i >> 9;                 // wd tile
            int off = i & 511;
            sBt[i] = Bp[(unsigned)(((d0 >> 5) + tw) * FDIM + f) * 512 + off];
        }
    }
    __syncthreads();

    int accL[4][4];
    int accH[4][4];
    #pragma unroll
    for (int nt = 0; nt < 4; nt++)
        #pragma unroll
        for (int i = 0; i < 4; i++) { accL[nt][i] = 0; accH[nt][i] = 0; }

    int aBase = wb * 256;
    int bBase = wd * 512;
    #pragma unroll
    for (int q = 0; q < 4; q++) {
        uint4 al0 = sALo[aBase + q * 32 + lane];
        uint4 al1 = sALo[aBase + (4 + q) * 32 + lane];
        uint4 ah0 = sAHi[aBase + q * 32 + lane];
        uint4 ah1 = sAHi[aBase + (4 + q) * 32 + lane];
        uint4 bq0 = sBt[bBase + (0 * 4 + q) * 32 + lane];
        uint4 bq1 = sBt[bBase + (1 * 4 + q) * 32 + lane];
        uint4 bq2 = sBt[bBase + (2 * 4 + q) * 32 + lane];
        uint4 bq3 = sBt[bBase + (3 * 4 + q) * 32 + lane];
        imma16832(accL[0][0], accL[0][1], accL[0][2], accL[0][3], al0.x, al1.x, al0.y, al1.y, bq0.x, bq0.y);
        imma16832(accL[1][0], accL[1][1], accL[1][2], accL[1][3], al0.x, al1.x, al0.y, al1.y, bq1.x, bq1.y);
        imma16832(accL[2][0], accL[2][1], accL[2][2], accL[2][3], al0.x, al1.x, al0.y, al1.y, bq2.x, bq2.y);
        imma16832(accL[3][0], accL[3][1], accL[3][2], accL[3][3], al0.x, al1.x, al0.y, al1.y, bq3.x, bq3.y);
        imma16832(accH[0][0], accH[0][1], accH[0][2], accH[0][3], ah0.x, ah1.x, ah0.y, ah1.y, bq0.x, bq0.y);
        imma16832(accH[1][0], accH[1][1], accH[1][2], accH[1][3], ah0.x, ah1.x, ah0.y, ah1.y, bq1.x, bq1.y);
        imma16832(accH[2][0], accH[2][1], accH[2][2], accH[2][3], ah0.x, ah1.x, ah0.y, ah1.y, bq2.x, bq2.y);
        imma16832(accH[3][0], accH[3][1], accH[3][2], accH[3][3], ah0.x, ah1.x, ah0.y, ah1.y, bq3.x, bq3.y);
        imma16832(accL[0][0], accL[0][1], accL[0][2], accL[0][3], al0.z, al1.z, al0.w, al1.w, bq0.z, bq0.w);
        imma16832(accL[1][0], accL[1][1], accL[1][2], accL[1][3], al0.z, al1.z, al0.w, al1.w, bq1.z, bq1.w);
        imma16832(accL[2][0], accL[2][1], accL[2][2], accL[2][3], al0.z, al1.z, al0.w, al1.w, bq2.z, bq2.w);
        imma16832(accL[3][0], accL[3][1], accL[3][2], accL[3][3], al0.z, al1.z, al0.w, al1.w, bq3.z, bq3.w);
        imma16832(accH[0][0], accH[0][1], accH[0][2], accH[0][3], ah0.z, ah1.z, ah0.w, ah1.w, bq0.z, bq0.w);
        imma16832(accH[1][0], accH[1][1], accH[1][2], accH[1][3], ah0.z, ah1.z, ah0.w, ah1.w, bq1.z, bq1.w);
        imma16832(accH[2][0], accH[2][1], accH[2][2], accH[2][3], ah0.z, ah1.z, ah0.w, ah1.w, bq2.z, bq2.w);
        imma16832(accH[3][0], accH[3][1], accH[3][2], accH[3][3], ah0.z, ah1.z, ah0.w, ah1.w, bq3.z, bq3.w);
    }
    __syncthreads();   // all smem reads done before epilogue overwrites it

    int bl0 = wb * 16 + g;
    int bl1 = bl0 + 8;
    #pragma unroll
    for (int nt = 0; nt < 4; nt++) {
        int dc = wd * 32 + nt * 8 + tig * 2;
        int o00 = accL[nt][0] + (accH[nt][0] << 7);
        int o01 = accL[nt][1] + (accH[nt][1] << 7);
        int o10 = accL[nt][2] + (accH[nt][2] << 7);
        int o11 = accL[nt][3] + (accH[nt][3] << 7);
        sB[bl0][dc]     = (unsigned char)((o00 < 0 ? 1u : 0u) | (o00 != 0 ? 2u : 0u));
        sB[bl0][dc + 1] = (unsigned char)((o01 < 0 ? 1u : 0u) | (o01 != 0 ? 2u : 0u));
        sB[bl1][dc]     = (unsigned char)((o10 < 0 ? 1u : 0u) | (o10 != 0 ? 2u : 0u));
        sB[bl1][dc + 1] = (unsigned char)((o11 < 0 ? 1u : 0u) | (o11 != 0 ? 2u : 0u));
    }
    __syncthreads();

    int ldiff = 0;
    int t = threadIdx.x;
    if (t < 128) {
        int bl = t >> 1;
        int wsel = t & 1;
        unsigned ws = 0, wm = 0;
        #pragma unroll
        for (int n = 0; n < 32; n++) {
            unsigned byte = sB[bl][wsel * 32 + n];
            ws |= (byte & 1u) << n;
            wm |= ((byte >> 1) & 1u) << n;
        }
        size_t o = ((size_t)(b0 + bl) * FDIM + f) * WDIM + (d0 >> 5) + wsel;
        if (ws != g_eS[o] || wm != g_eM[o]) ldiff = 1;
        g_eS[o] = ws;
        g_eM[o] = wm;
    }
    last_block_step(ldiff, 2048);
}

// ---------------------------------------------------------------------------
// argmax over m (first-index tie-break) + write k.  Output dtype: float32.
// ---------------------------------------------------------------------------
__global__ void argmax_kernel(float* __restrict__ out, int out_size) {
    int gtid = blockIdx.x * blockDim.x + threadIdx.x;
    int w = gtid >> 5;
    int lane = gtid & 31;
    if (w < BDIM * FDIM) {
        const float* srow = g_sim + (size_t)w * MDIM;
        float bv = -3.0e38f;
        int bi = 0;
        for (int m = lane; m < MDIM; m += 32) {
            float v = srow[m];
            if (v > bv) { bv = v; bi = m; }
        }
        for (int off = 16; off > 0; off >>= 1) {
            float ov = __shfl_down_sync(0xffffffffu, bv, off);
            int oi = __shfl_down_sync(0xffffffffu, bi, off);
            if (ov > bv || (ov == bv && oi < bi)) { bv = ov; bi = oi; }
        }
        if (lane == 0) out[w] = (float)bi;
    }
    if (gtid == 0 && out_size > BDIM * FDIM) out[BDIM * FDIM] = (float)g_k;
}

// ---------------------------------------------------------------------------
extern "C" void kernel_launch(void* const* d_in, const int* in_sizes, int n_in,
                              void* d_out, int out_size) {
    const float* inp;
    const float* cb;
    if (in_sizes[0] < in_sizes[1]) { inp = (const float*)d_in[0]; cb = (const float*)d_in[1]; }
    else                           { inp = (const float*)d_in[1]; cb = (const float*)d_in[0]; }
    float* out = (float*)d_out;

    colsum_pf_kernel<<<32, 256>>>(cb);
    pack_all_kernel<<<41984, 256>>>(cb, inp);
    gemm1_f32_kernel<<<dim3(16, FDIM, 8), 256>>>(cb, inp);
    gemm2_f32_kernel<<<dim3(DDIM / 64, BDIM / 64, FDIM), 256>>>(cb);   // ncu capture (#3)

    for (int it = 1; it < NITERS; it++) {
        gemm1_packed_kernel<<<dim3(BDIM / 32, MDIM / 32, FDIM), 256>>>(0, 1);
        gemm2_imma_kernel<<<dim3(DDIM / 64, BDIM / 64, FDIM), 256>>>();
    }

    gemm1_packed_kernel<<<dim3(BDIM / 32, MDIM / 32, FDIM), 256>>>(1, 0);
    argmax_kernel<<<(BDIM * FDIM * 32) / 256, 256>>>(out, out_size);
}

// round 14
// speedup vs baseline: 1.4521x; 1.0482x over previous
#include <cuda_runtime.h>
#include <cuda_bf16.h>
#include <cstdint>

#define BDIM 256
#define FDIM 4
#define MDIM 256
#define DDIM 8192
#define WDIM 256          // DDIM/32 packed words
#define NITERS 10

// Scratch (device globals -- allocation is forbidden)
__device__ float g_sim[BDIM * FDIM * MDIM];       // 1 MB
__device__ float g_colsum[FDIM * DDIM];
__device__ float g_P[FDIM * DDIM];
__device__ unsigned g_eS[BDIM * FDIM * WDIM];     // packed est sign bits
__device__ unsigned g_eM[BDIM * FDIM * WDIM];     // packed est nonzero mask
__device__ unsigned g_iS[BDIM * WDIM];            // packed inp sign bits
__device__ unsigned g_cbSt[FDIM * WDIM * MDIM];   // cb sign bits transposed [f][w][m]
__device__ __nv_bfloat16 g_simB[BDIM * FDIM * 512];        // A: [lo(256) | 128*hi(256)]
__device__ __nv_bfloat16 g_cbB[(size_t)FDIM * DDIM * 256]; // cb transposed [f][d][m] bf16
__device__ int g_done;
__device__ int g_diff;
__device__ int g_k;
__device__ unsigned g_ticket;

// ---------------------------------------------------------------------------
// ONE setup kernel: colsum+P+zero+flags (32 blocks), cb signs (32768),
// inp signs (8192), cb bf16 transpose (1024).  grid = 42016.
// ---------------------------------------------------------------------------
__global__ void setup_kernel(const float* __restrict__ cb,
                             const float* __restrict__ inp) {
    __shared__ signed char t[32][260];
    int bx = blockIdx.x;
    if (bx < 32) {
        int d = bx * 256 + threadIdx.x;
        float s[4];
        #pragma unroll
        for (int f = 0; f < 4; f++) {
            const float* p = cb + ((size_t)f * MDIM) * DDIM + d;
            float acc = 0.f;
            for (int m = 0; m < MDIM; m++) acc += p[(size_t)m * DDIM];
            s[f] = acc;
            g_colsum[f * DDIM + d] = acc;
        }
        g_P[d]            = (s[1] * s[2]) * s[3];
        g_P[DDIM + d]     = (s[0] * s[2]) * s[3];
        g_P[2 * DDIM + d] = (s[0] * s[1]) * s[3];
        g_P[3 * DDIM + d] = (s[0] * s[1]) * s[2];
        for (int i = d; i < BDIM * FDIM * MDIM; i += 32 * 256) g_sim[i] = 0.f;
        if (d == 0) { g_done = 0; g_diff = 0; g_k = 0; g_ticket = 0; }
    } else if (bx < 32 + 32768) {
        int idx = (bx - 32) * 256 + threadIdx.x;       // (f*M+m)*8192 + d
        float v = cb[idx];
        unsigned neg = __ballot_sync(0xffffffffu, v < 0.f);
        if ((threadIdx.x & 31) == 0) {
            int fm = idx >> 13;
            int d = idx & (DDIM - 1);
            g_cbSt[((size_t)(fm >> 8) * WDIM + (d >> 5)) * MDIM + (fm & 255)] = neg;
        }
    } else if (bx < 32 + 32768 + 8192) {
        int idx = (bx - 32800) * 256 + threadIdx.x;    // b*8192 + d
        unsigned neg = __ballot_sync(0xffffffffu, inp[idx] < 0.f);
        if ((threadIdx.x & 31) == 0) {
            int b = idx >> 13;
            int d = idx & (DDIM - 1);
            g_iS[(size_t)b * WDIM + (d >> 5)] = neg;
        }
    } else {
        int pb = bx - 40992;                           // 0..1023: (dblock, f)
        int d0 = (pb >> 2) * 32;
        int f = pb & 3;
        for (int idx = threadIdx.x; idx < 256 * 32; idx += 256) {
            int m = idx >> 5;
            int dl = idx & 31;
            t[dl][m] = (signed char)cb[((size_t)f * MDIM + m) * DDIM + d0 + dl];
        }
        __syncthreads();
        for (int idx = threadIdx.x; idx < 32 * 256; idx += 256) {
            int dl = idx >> 8;
            int m = idx & 255;
            g_cbB[((size_t)f * DDIM + d0 + dl) * 256 + m] =
                __float2bfloat16((float)t[dl][m]);
        }
    }
}

// ---------------------------------------------------------------------------
__device__ __forceinline__ void last_block_step(int ldiff, int nblocks) {
    int any = __syncthreads_or(ldiff);
    if (threadIdx.x == 0) {
        if (any) atomicOr(&g_diff, 1);
        __threadfence();
        unsigned tk = atomicAdd(&g_ticket, 1u);
        if (tk == (unsigned)(nblocks - 1)) {
            g_ticket = 0;
            g_k = g_k + 1;
            if (atomicAdd(&g_diff, 0) == 0) g_done = 1;
            g_diff = 0;
        }
    }
}

// ---------------------------------------------------------------------------
// stage-0 GEMM1 (float, split-K=8 atomicAdd), A = inp * P on the fly. (proven)
// ---------------------------------------------------------------------------
__global__ void gemm1_f32_kernel(const float* __restrict__ cb,
                                 const float* __restrict__ inp) {
    if (g_done) return;
    int bt = blockIdx.x >> 2;
    int mt = blockIdx.x & 3;
    int f = blockIdx.y;
    int b0 = bt * 64;
    int m0 = mt * 64;
    int k0 = blockIdx.z * (DDIM / 8);

    __shared__ __align__(16) float As[32][68];
    __shared__ __align__(16) float Bs[32][68];

    int tx = threadIdx.x & 15;
    int ty = threadIdx.x >> 4;

    float acc[4][4];
    for (int i = 0; i < 4; i++)
        for (int j = 0; j < 4; j++) acc[i][j] = 0.f;

    for (int kk = 0; kk < DDIM / 8; kk += 32) {
        for (int e = threadIdx.x; e < 2048; e += 256) {
            int r = e >> 5;
            int c = e & 31;
            int d = k0 + kk + c;
            As[c][r] = inp[(size_t)(b0 + r) * DDIM + d] * g_P[(size_t)f * DDIM + d];
            Bs[c][r] = cb[((size_t)f * MDIM + m0 + r) * DDIM + d];
        }
        __syncthreads();
        #pragma unroll
        for (int k = 0; k < 32; k++) {
            float4 av = *(const float4*)&As[k][tx * 4];
            float4 bv = *(const float4*)&Bs[k][ty * 4];
            acc[0][0] += av.x * bv.x; acc[0][1] += av.x * bv.y; acc[0][2] += av.x * bv.z; acc[0][3] += av.x * bv.w;
            acc[1][0] += av.y * bv.x; acc[1][1] += av.y * bv.y; acc[1][2] += av.y * bv.z; acc[1][3] += av.y * bv.w;
            acc[2][0] += av.z * bv.x; acc[2][1] += av.z * bv.y; acc[2][2] += av.z * bv.z; acc[2][3] += av.z * bv.w;
            acc[3][0] += av.w * bv.x; acc[3][1] += av.w * bv.y; acc[3][2] += av.w * bv.z; acc[3][3] += av.w * bv.w;
        }
        __syncthreads();
    }
    for (int i = 0; i < 4; i++)
        for (int j = 0; j < 4; j++) {
            int b = b0 + tx * 4 + i;
            int m = m0 + ty * 4 + j;
            atomicAdd(&g_sim[((size_t)b * FDIM + f) * MDIM + m], acc[i][j]);
        }
}

// ---------------------------------------------------------------------------
// stage-0 GEMM2 (float) + sign + convergence + PACKED est + step. (proven)
// ---------------------------------------------------------------------------
__global__ void gemm2_f32_kernel(const float* __restrict__ cb) {
    if (g_done) return;
    int f = blockIdx.z;
    int b0 = blockIdx.y * 64;
    int d0 = blockIdx.x * 64;

    __shared__ __align__(16) float As[32][68];
    __shared__ __align__(16) float Bs[32][68];
    __shared__ unsigned char nibS[64][16];
    __shared__ unsigned char nibM[64][16];

    int tx = threadIdx.x & 15;
    int ty = threadIdx.x >> 4;

    float acc[4][4];
    for (int i = 0; i < 4; i++)
        for (int j = 0; j < 4; j++) acc[i][j] = 0.f;

    for (int mb = 0; mb < MDIM; mb += 32) {
        for (int e = threadIdx.x; e < 2048; e += 256) {
            int r = e >> 5;
            int c = e & 31;
            As[c][r] = g_sim[((size_t)(b0 + r) * FDIM + f) * MDIM + mb + c];
        }
        for (int e = threadIdx.x; e < 2048; e += 256) {
            int m = e >> 6;
            int dd = e & 63;
            Bs[m][dd] = cb[((size_t)f * MDIM + mb + m) * DDIM + d0 + dd];
        }
        __syncthreads();
        #pragma unroll
        for (int m = 0; m < 32; m++) {
            float4 av = *(const float4*)&As[m][ty * 4];
            float4 bv = *(const float4*)&Bs[m][tx * 4];
            acc[0][0] += av.x * bv.x; acc[0][1] += av.x * bv.y; acc[0][2] += av.x * bv.z; acc[0][3] += av.x * bv.w;
            acc[1][0] += av.y * bv.x; acc[1][1] += av.y * bv.y; acc[1][2] += av.y * bv.z; acc[1][3] += av.y * bv.w;
            acc[2][0] += av.z * bv.x; acc[2][1] += av.z * bv.y; acc[2][2] += av.z * bv.z; acc[2][3] += av.z * bv.w;
            acc[3][0] += av.w * bv.x; acc[3][1] += av.w * bv.y; acc[3][2] += av.w * bv.z; acc[3][3] += av.w * bv.w;
        }
        __syncthreads();
    }

    int ldiff = 0;
    #pragma unroll
    for (int i = 0; i < 4; i++) {
        unsigned sn = 0, mn = 0;
        #pragma unroll
        for (int j = 0; j < 4; j++) {
            float v = acc[i][j];
            float s = (v > 0.f) ? 1.f : ((v < 0.f) ? -1.f : 0.f);
            int d = d0 + tx * 4 + j;
            if (s != g_colsum[(size_t)f * DDIM + d]) ldiff = 1;
            if (v < 0.f) sn |= (1u << j);
            if (v != 0.f) mn |= (1u << j);
        }
        nibS[ty * 4 + i][tx] = (unsigned char)sn;
        nibM[ty * 4 + i][tx] = (unsigned char)mn;
    }
    __syncthreads();

    int t = threadIdx.x;
    if (t < 128) {
        int bl = t >> 1;
        int wsel = t & 1;
        unsigned ws = 0, wm = 0;
        #pragma unroll
        for (int n = 0; n < 8; n++) {
            ws |= (unsigned)nibS[bl][wsel * 8 + n] << (4 * n);
            wm |= (unsigned)nibM[bl][wsel * 8 + n] << (4 * n);
        }
        size_t o = ((size_t)(b0 + bl) * FDIM + f) * WDIM + (d0 >> 5) + wsel;
        g_eS[o] = ws;
        g_eM[o] = wm;
    }
    last_block_step(ldiff, 2048);
}

// ---------------------------------------------------------------------------
// packed GEMM1 with FUSED newest (src_est=0) or est source (src_est=1).
// src_est=0: writes bf16 A planes [lo | 128*hi].  src_est=1: writes f32 sim.
// ---------------------------------------------------------------------------
__global__ void gemm1_packed_kernel(int src_est, int respect_done) {
    if (respect_done && g_done) return;
    int b0 = blockIdx.x * 32;
    int m0 = blockIdx.y * 32;
    int f = blockIdx.z;
    int f1 = (f + 1) & 3, f2 = (f + 2) & 3, f3 = (f + 3) & 3;

    __shared__ unsigned AS[32][33];
    __shared__ unsigned AM[32][33];
    __shared__ unsigned BS[32][33];

    int tx = threadIdx.x & 15;
    int ty = threadIdx.x >> 4;

    int acc[2][2] = {{0, 0}, {0, 0}};
    int accM[2] = {0, 0};

    for (int w0 = 0; w0 < WDIM; w0 += 32) {
        if (src_est) {
            for (int e = threadIdx.x; e < 1024; e += 256) {
                int r = e >> 5;
                int c = e & 31;
                size_t src = ((size_t)(b0 + r) * FDIM + f) * WDIM + w0 + c;
                AS[c][r] = g_eS[src];
                AM[c][r] = g_eM[src];
            }
        } else {
            for (int e = threadIdx.x; e < 1024; e += 256) {
                int r = e >> 5;
                int c = e & 31;
                int b = b0 + r;
                int w = w0 + c;
                size_t base = ((size_t)b * FDIM) * WDIM + w;
                unsigned so1 = g_eS[base + (size_t)f1 * WDIM];
                unsigned so2 = g_eS[base + (size_t)f2 * WDIM];
                unsigned so3 = g_eS[base + (size_t)f3 * WDIM];
                unsigned mo1 = g_eM[base + (size_t)f1 * WDIM];
                unsigned mo2 = g_eM[base + (size_t)f2 * WDIM];
                unsigned mo3 = g_eM[base + (size_t)f3 * WDIM];
                unsigned Mf = mo1 & mo2 & mo3;
                unsigned Sf = (g_iS[(size_t)b * WDIM + w] ^ so1 ^ so2 ^ so3) & Mf;
                AS[c][r] = Sf;
                AM[c][r] = Mf;
            }
        }
        for (int e = threadIdx.x; e < 1024; e += 256) {
            int w = e >> 5;
            int m = e & 31;
            BS[w][m] = g_cbSt[((size_t)f * WDIM + w0 + w) * MDIM + m0 + m];
        }
        __syncthreads();
        #pragma unroll
        for (int w = 0; w < 32; w++) {
            unsigned sa0 = AS[w][tx * 2 + 0];
            unsigned sa1 = AS[w][tx * 2 + 1];
            unsigned ma0 = AM[w][tx * 2 + 0];
            unsigned ma1 = AM[w][tx * 2 + 1];
            unsigned sb0 = BS[w][ty * 2 + 0];
            unsigned sb1 = BS[w][ty * 2 + 1];
            accM[0] += __popc(ma0);
            accM[1] += __popc(ma1);
            acc[0][0] += __popc((sa0 ^ sb0) & ma0);
            acc[0][1] += __popc((sa0 ^ sb1) & ma0);
            acc[1][0] += __popc((sa1 ^ sb0) & ma1);
            acc[1][1] += __popc((sa1 ^ sb1) & ma1);
        }
        __syncthreads();
    }

    #pragma unroll
    for (int i = 0; i < 2; i++) {
        int b = b0 + tx * 2 + i;
        size_t base = ((size_t)b * FDIM + f) * 512;
        #pragma unroll
        for (int j = 0; j < 2; j++) {
            int m = m0 + ty * 2 + j;
            int sim = accM[i] - 2 * acc[i][j];
            if (src_est) {
                g_sim[((size_t)b * FDIM + f) * MDIM + m] = (float)sim;
            } else {
                int hi = (sim + 64) >> 7;        // hi in [-64,64]
                int lo = sim - (hi << 7);        // lo in [-64,63]
                g_simB[base + m] = __float2bfloat16((float)lo);
                g_simB[base + 256 + m] = __float2bfloat16((float)(hi << 7));
            }
        }
    }
}

// ---------------------------------------------------------------------------
// packed GEMM2 via bf16 mma.sync.m16n8k16 (K=512 fused lo|hi planes).
// Block: 128 b-rows x 64 d-cols, f fixed.  grid (128, 2, F).  256 thr = 8 warps
// (wb 0..3: 32 b-rows; wd 0..1: 32 d-cols).  K in 8 smem chunks of 64.
// smem row stride 36 u32 -> LDS bank = 4g+tig (conflict-free).
// Exact: lo, 128*hi exact bf16; f32 accumulation of ints < 2^21 exact.
// ---------------------------------------------------------------------------
__device__ __forceinline__ void hmma16816(float& c0, float& c1, float& c2, float& c3,
                                          unsigned a0, unsigned a1, unsigned a2, unsigned a3,
                                          unsigned b0, unsigned b1) {
    asm volatile(
        "mma.sync.aligned.m16n8k16.row.col.f32.bf16.bf16.f32 "
        "{%0,%1,%2,%3}, {%4,%5,%6,%7}, {%8,%9}, {%0,%1,%2,%3};\n"
        : "+f"(c0), "+f"(c1), "+f"(c2), "+f"(c3)
        : "r"(a0), "r"(a1), "r"(a2), "r"(a3), "r"(b0), "r"(b1));
}

__global__ void gemm2_bf16_kernel() {
    if (g_done) return;
    __shared__ __align__(16) unsigned sA[128 * 36];   // 128 rows x (32 data + 4 pad)
    __shared__ __align__(16) unsigned sB[64 * 36];    // 64 rows x (32 data + 4 pad)
    __shared__ unsigned char sSM[128][64];            // epilogue sign/mask bytes

    int f = blockIdx.z;
    int d0 = blockIdx.x * 64;
    int b0 = blockIdx.y * 128;
    int tid = threadIdx.x;
    int wid = tid >> 5;
    int lane = tid & 31;
    int g = lane >> 2;
    int tig = lane & 3;
    int wb = wid & 3;     // 32 b-rows
    int wd = wid >> 1 & 0;  // placeholder (computed below)
    wd = wid >> 2;        // 0..1: 32 d-cols

    float acc[2][4][4];
    #pragma unroll
    for (int mt = 0; mt < 2; mt++)
        #pragma unroll
        for (int nt = 0; nt < 4; nt++)
            #pragma unroll
            for (int i = 0; i < 4; i++) acc[mt][nt][i] = 0.f;

    const uint4* A4 = (const uint4*)g_simB;   // 64 uint4 per (b,f) row
    const uint4* B4 = (const uint4*)g_cbB;    // 32 uint4 per (f,d) row
    uint4* sA4 = (uint4*)sA;                  // row stride 9 uint4
    uint4* sB4 = (uint4*)sB;

    for (int kc = 0; kc < 8; kc++) {
        // stage A chunk: 128 rows x 64 bf16 (8 uint4/row)
        for (int i = tid; i < 1024; i += 256) {
            int row = i >> 3;
            int un = i & 7;
            sA4[row * 9 + un] = A4[((size_t)(b0 + row) * FDIM + f) * 64 + kc * 8 + un];
        }
        // stage B chunk: 64 rows x 64 bf16
        for (int i = tid; i < 512; i += 256) {
            int row = i >> 3;
            int un = i & 7;
            sB4[row * 9 + un] = B4[((size_t)f * DDIM + d0 + row) * 32 + (kc & 3) * 8 + un];
        }
        __syncthreads();
        #pragma unroll
        for (int s = 0; s < 4; s++) {    // 4 ksteps of 16 within chunk
            unsigned a[2][4];
            #pragma unroll
            for (int mt = 0; mt < 2; mt++) {
                int r = wb * 32 + mt * 16 + g;
                a[mt][0] = sA[r * 36 + s * 8 + tig];
                a[mt][1] = sA[(r + 8) * 36 + s * 8 + tig];
                a[mt][2] = sA[r * 36 + s * 8 + tig + 4];
                a[mt][3] = sA[(r + 8) * 36 + s * 8 + tig + 4];
            }
            #pragma unroll
            for (int nt = 0; nt < 4; nt++) {
                int rd = wd * 32 + nt * 8 + g;
                unsigned bb0 = sB[rd * 36 + s * 8 + tig];
                unsigned bb1 = sB[rd * 36 + s * 8 + tig + 4];
                #pragma unroll
                for (int mt = 0; mt < 2; mt++)
                    hmma16816(acc[mt][nt][0], acc[mt][nt][1], acc[mt][nt][2], acc[mt][nt][3],
                              a[mt][0], a[mt][1], a[mt][2], a[mt][3], bb0, bb1);
            }
        }
        __syncthreads();
    }

    // epilogue: values are exact integers in f32.
    #pragma unroll
    for (int mt = 0; mt < 2; mt++) {
        int r0 = wb * 32 + mt * 16 + g;
        #pragma unroll
        for (int nt = 0; nt < 4; nt++) {
            int c0 = wd * 32 + nt * 8 + tig * 2;
            float v0 = acc[mt][nt][0];
            float v1 = acc[mt][nt][1];
            float v2 = acc[mt][nt][2];
            float v3 = acc[mt][nt][3];
            sSM[r0][c0]         = (unsigned char)((v0 < 0.f ? 1u : 0u) | (v0 != 0.f ? 2u : 0u));
            sSM[r0][c0 + 1]     = (unsigned char)((v1 < 0.f ? 1u : 0u) | (v1 != 0.f ? 2u : 0u));
            sSM[r0 + 8][c0]     = (unsigned char)((v2 < 0.f ? 1u : 0u) | (v2 != 0.f ? 2u : 0u));
            sSM[r0 + 8][c0 + 1] = (unsigned char)((v3 < 0.f ? 1u : 0u) | (v3 != 0.f ? 2u : 0u));
        }
    }
    __syncthreads();

    int ldiff = 0;
    {
        int row = tid >> 1;          // 0..127
        int wsel = tid & 1;
        unsigned ws = 0, wm = 0;
        #pragma unroll
        for (int n = 0; n < 32; n++) {
            unsigned byte = sSM[row][wsel * 32 + n];
            ws |= (byte & 1u) << n;
            wm |= ((byte >> 1) & 1u) << n;
        }
        size_t o = ((size_t)(b0 + row) * FDIM + f) * WDIM + (d0 >> 5) + wsel;
        if (ws != g_eS[o] || wm != g_eM[o]) ldiff = 1;
        g_eS[o] = ws;
        g_eM[o] = wm;
    }
    last_block_step(ldiff, 1024);
}

// ---------------------------------------------------------------------------
// argmax over m (first-index tie-break) + write k.  Output dtype: float32.
// ---------------------------------------------------------------------------
__global__ void argmax_kernel(float* __restrict__ out, int out_size) {
    int gtid = blockIdx.x * blockDim.x + threadIdx.x;
    int w = gtid >> 5;
    int lane = gtid & 31;
    if (w < BDIM * FDIM) {
        const float* srow = g_sim + (size_t)w * MDIM;
        float bv = -3.0e38f;
        int bi = 0;
        for (int m = lane; m < MDIM; m += 32) {
            float v = srow[m];
            if (v > bv) { bv = v; bi = m; }
        }
        for (int off = 16; off > 0; off >>= 1) {
            float ov = __shfl_down_sync(0xffffffffu, bv, off);
            int oi = __shfl_down_sync(0xffffffffu, bi, off);
            if (ov > bv || (ov == bv && oi < bi)) { bv = ov; bi = oi; }
        }
        if (lane == 0) out[w] = (float)bi;
    }
    if (gtid == 0 && out_size > BDIM * FDIM) out[BDIM * FDIM] = (float)g_k;
}

// ---------------------------------------------------------------------------
extern "C" void kernel_launch(void* const* d_in, const int* in_sizes, int n_in,
                              void* d_out, int out_size) {
    const float* inp;
    const float* cb;
    if (in_sizes[0] < in_sizes[1]) { inp = (const float*)d_in[0]; cb = (const float*)d_in[1]; }
    else                           { inp = (const float*)d_in[1]; cb = (const float*)d_in[0]; }
    float* out = (float*)d_out;

    // launch #0..#3: setup, g1f32, g2f32, g1packed (ncu capture = index 3)
    setup_kernel<<<42016, 256>>>(cb, inp);
    gemm1_f32_kernel<<<dim3(16, FDIM, 8), 256>>>(cb, inp);
    gemm2_f32_kernel<<<dim3(DDIM / 64, BDIM / 64, FDIM), 256>>>(cb);

    for (int it = 1; it < NITERS; it++) {
        gemm1_packed_kernel<<<dim3(BDIM / 32, MDIM / 32, FDIM), 256>>>(0, 1);
        gemm2_bf16_kernel<<<dim3(DDIM / 64, BDIM / 128, FDIM), 256>>>();
    }

    gemm1_packed_kernel<<<dim3(BDIM / 32, MDIM / 32, FDIM), 256>>>(1, 0);
    argmax_kernel<<<(BDIM * FDIM * 32) / 256, 256>>>(out, out_size);
}